// round 3
// baseline (speedup 1.0000x reference)
#include <cuda_runtime.h>
#include <math.h>

// Problem constants
namespace {
constexpr int B = 64, T = 256, E = 512, H = 512, TAGS = 50;
constexpr int G = 4 * H;   // 2048 (gate dim)
constexpr int M = T * B;   // 16384 rows
constexpr int NBLK_PER_DIR = 64;   // persistent blocks per direction
}

// Scratch (static device arrays — no cudaMalloc allowed)
__device__ float g_xs[M * E];        //  32 MB  embedded inputs [T*B, E]
__device__ float g_pre_f[M * G];     // 128 MB  x@Wih^T + biases (fwd)
__device__ float g_pre_b[M * G];     // 128 MB  (bwd)
__device__ float g_out1[M * 2 * H];  //  64 MB  layer-1 output [T*B, 2H]
__device__ float g_out2[M * 2 * H];  //  64 MB  layer-2 output
__device__ float g_hT[2][2][H * B];  // h double buffer, TRANSPOSED [parity][dir][j][b]
__device__ unsigned g_barcnt[2];               // per-dir barrier arrival counter
__device__ volatile unsigned g_bargen[2];      // per-dir barrier generation

// ---------------------------------------------------------------------------
__global__ void init_layer_kernel() {
  int i = blockIdx.x * blockDim.x + threadIdx.x;
  float* ht = &g_hT[0][0][0];
  if (i < 2 * 2 * H * B) ht[i] = 0.f;
  if (i < 2) { g_barcnt[i] = 0; g_bargen[i] = 0; }
}

// Embedding gather: g_xs[(t*B+b)*E + :] = emb[x[b,t], :]
__global__ void embed_kernel(const int* __restrict__ x,
                             const float* __restrict__ emb) {
  int row = blockIdx.x;        // t*B + b
  int t = row >> 6;
  int b = row & 63;
  int tok = x[b * T + t];
  const float4* src = reinterpret_cast<const float4*>(emb + (size_t)tok * E);
  float4* dst = reinterpret_cast<float4*>(g_xs + (size_t)row * E);
  dst[threadIdx.x] = src[threadIdx.x];   // 128 threads * float4 = 512 floats
}

// ---------------------------------------------------------------------------
// C[M, 2048] = A[M, K] @ W[2048, K]^T + (b1 + b2)
template <int K>
__global__ __launch_bounds__(256)
void sgemm_bias_kernel(const float* __restrict__ A,
                       const float* __restrict__ W,
                       const float* __restrict__ b1,
                       const float* __restrict__ b2,
                       float* __restrict__ C) {
  __shared__ float As[8][132];
  __shared__ float Ws[8][132];
  const int bm = blockIdx.y << 7;
  const int bn = blockIdx.x << 7;
  const int tid = threadIdx.x;
  const int tm = (tid >> 4) << 3;
  const int tn = (tid & 15) << 3;
  const int lrow = tid >> 1;
  const int lc4 = (tid & 1) << 2;
  const float* Ap = A + (size_t)(bm + lrow) * K + lc4;
  const float* Wp = W + (size_t)(bn + lrow) * K + lc4;

  float acc[8][8];
#pragma unroll
  for (int i = 0; i < 8; i++)
#pragma unroll
    for (int j = 0; j < 8; j++) acc[i][j] = 0.f;

  float4 av = *reinterpret_cast<const float4*>(Ap);
  float4 wv = *reinterpret_cast<const float4*>(Wp);

  for (int k0 = 0; k0 < K; k0 += 8) {
    __syncthreads();
    As[lc4 + 0][lrow] = av.x; As[lc4 + 1][lrow] = av.y;
    As[lc4 + 2][lrow] = av.z; As[lc4 + 3][lrow] = av.w;
    Ws[lc4 + 0][lrow] = wv.x; Ws[lc4 + 1][lrow] = wv.y;
    Ws[lc4 + 2][lrow] = wv.z; Ws[lc4 + 3][lrow] = wv.w;
    __syncthreads();
    if (k0 + 8 < K) {
      av = *reinterpret_cast<const float4*>(Ap + k0 + 8);
      wv = *reinterpret_cast<const float4*>(Wp + k0 + 8);
    }
#pragma unroll
    for (int kk = 0; kk < 8; kk++) {
      float ra[8], rw[8];
      *reinterpret_cast<float4*>(&ra[0]) = *reinterpret_cast<const float4*>(&As[kk][tm]);
      *reinterpret_cast<float4*>(&ra[4]) = *reinterpret_cast<const float4*>(&As[kk][tm + 4]);
      *reinterpret_cast<float4*>(&rw[0]) = *reinterpret_cast<const float4*>(&Ws[kk][tn]);
      *reinterpret_cast<float4*>(&rw[4]) = *reinterpret_cast<const float4*>(&Ws[kk][tn + 4]);
#pragma unroll
      for (int i = 0; i < 8; i++)
#pragma unroll
        for (int j = 0; j < 8; j++) acc[i][j] = fmaf(ra[i], rw[j], acc[i][j]);
    }
  }

  float bb[8];
#pragma unroll
  for (int j = 0; j < 8; j++) {
    int col = bn + tn + j;
    bb[j] = b1[col] + b2[col];
  }
#pragma unroll
  for (int i = 0; i < 8; i++) {
    size_t crow = (size_t)(bm + tm + i) * G + (bn + tn);
    float4 v0 = make_float4(acc[i][0] + bb[0], acc[i][1] + bb[1],
                            acc[i][2] + bb[2], acc[i][3] + bb[3]);
    float4 v1 = make_float4(acc[i][4] + bb[4], acc[i][5] + bb[5],
                            acc[i][6] + bb[6], acc[i][7] + bb[7]);
    *reinterpret_cast<float4*>(&C[crow]) = v0;
    *reinterpret_cast<float4*>(&C[crow + 4]) = v1;
  }
}

// ---------------------------------------------------------------------------
__device__ __forceinline__ float sigf(float x) {
  return 1.f / (1.f + __expf(-x));
}
// Packed fp32x2 FMA (Blackwell): d = a * b + d, lanes (lo, hi).
__device__ __forceinline__ void fma2(unsigned long long& d,
                                     unsigned long long a,
                                     unsigned long long b) {
  asm("fma.rn.f32x2 %0, %1, %2, %0;" : "+l"(d) : "l"(a), "l"(b));
}
__device__ __forceinline__ unsigned long long dup2(float x) {
  unsigned long long r;
  asm("mov.b64 %0, {%1, %1};" : "=l"(r) : "f"(x));
  return r;
}
__device__ __forceinline__ float2 up2(unsigned long long v) {
  float2 r;
  asm("mov.b64 {%0, %1}, %2;" : "=f"(r.x), "=f"(r.y) : "l"(v));
  return r;
}

// Persistent BiLSTM recurrence for one layer.
// Grid: 128 blocks (dir = bx>>6, j-tile = bx&63, 8 hidden units each).
// 128 threads: warp = b-group of 16 batches; lane = jp (4 j-pairs) x bp (8 b-pairs).
// Whh slice (32 rows x 512 k = 64KB) staged once into smem as
// w_s[k][jp*8 + g*2 + jhalf] so w arrives as natural (j0,j1) 64-bit pairs.
// Per thread per k: 2x LDS.128 (w), 1x LDG.64 (h pair, exactly-once per block),
// 2 dup movs, 8x fma.rn.f32x2 -> 16 FMAs. Acc pairs over (j0,j1).
__global__ __launch_bounds__(128, 1)
void lstm_persistent(const float* __restrict__ pre_f,
                     const float* __restrict__ pre_b,
                     const float* __restrict__ Whh_f,
                     const float* __restrict__ Whh_b,
                     float* __restrict__ out) {
  extern __shared__ float w_s[];   // [512][32] = 64KB
  const int dir = blockIdx.x >> 6;
  const int jt = blockIdx.x & 63;
  const int jblk = jt << 3;
  const int tid = threadIdx.x;
  const int lane = tid & 31;
  const int warp = tid >> 5;
  const int jp = lane >> 3;               // 0..3
  const int bpg = (warp << 3) + (lane & 7);  // 0..31 batch pair
  const int b0 = bpg << 1;
  const int jg = jblk + (jp << 1);
  const float* Whh = dir ? Whh_b : Whh_f;
  const float* pre = dir ? pre_b : pre_f;

  // Stage Whh slice, layout w_s[k*32 + jp*8 + g*2 + jh] = Whh[g*512+jblk+jl][k]
  // (lanes cover distinct rows for one k4 -> conflict-free STS)
  for (int e = tid; e < 4096; e += 128) {
    int rl = e & 31;                 // local row: g = rl>>3, jl = rl&7
    int k4 = (e >> 5) << 2;
    int g = rl >> 3, jl = rl & 7;
    float4 v = *reinterpret_cast<const float4*>(
        &Whh[((size_t)(g * 512 + jblk + jl)) * 512 + k4]);
    int col = ((jl >> 1) << 3) + (g << 1) + (jl & 1);
    w_s[(k4 + 0) * 32 + col] = v.x;
    w_s[(k4 + 1) * 32 + col] = v.y;
    w_s[(k4 + 2) * 32 + col] = v.z;
    w_s[(k4 + 3) * 32 + col] = v.w;
  }
  __syncthreads();

  float c00 = 0.f, c01 = 0.f, c10 = 0.f, c11 = 0.f;  // c[bhalf][jhalf]

  const float* wbase = w_s + (jp << 3);

  for (int t = 0; t < T; t++) {
    const int tt = dir ? (T - 1 - t) : t;
    const float* hp = g_hT[t & 1][dir];
    float* hn = g_hT[(t & 1) ^ 1][dir];

    unsigned long long acc[2][4];   // [bhalf][gate], lanes = (j0, j1)
#pragma unroll
    for (int i = 0; i < 2; i++)
#pragma unroll
      for (int g = 0; g < 4; g++) acc[i][g] = 0ull;

    const float2* hpp = reinterpret_cast<const float2*>(hp + b0);
#pragma unroll 4
    for (int k = 0; k < 512; k++) {
      const ulonglong2* wk =
          reinterpret_cast<const ulonglong2*>(wbase + k * 32);
      ulonglong2 wA = wk[0];   // (gate0 jpair, gate1 jpair)
      ulonglong2 wB = wk[1];   // (gate2 jpair, gate3 jpair)
      float2 hv = __ldcg(hpp + k * 32);   // (h[k][b0], h[k][b0+1])
      unsigned long long h0 = dup2(hv.x);
      unsigned long long h1 = dup2(hv.y);
      fma2(acc[0][0], wA.x, h0); fma2(acc[1][0], wA.x, h1);
      fma2(acc[0][1], wA.y, h0); fma2(acc[1][1], wA.y, h1);
      fma2(acc[0][2], wB.x, h0); fma2(acc[1][2], wB.x, h1);
      fma2(acc[0][3], wB.y, h0); fma2(acc[1][3], wB.y, h1);
    }

    // Epilogue: gates -> c, h for (j0,j1) x (b0,b0+1)
    float hh[2][2];   // [bhalf][jhalf]
#pragma unroll
    for (int i = 0; i < 2; i++) {
      int b = b0 + i;
      const float* pp = pre + ((size_t)tt * 64 + b) * 2048 + jg;
      float2 pi = *reinterpret_cast<const float2*>(pp);
      float2 pf = *reinterpret_cast<const float2*>(pp + 512);
      float2 pg = *reinterpret_cast<const float2*>(pp + 1024);
      float2 po = *reinterpret_cast<const float2*>(pp + 1536);
      float2 ai = up2(acc[i][0]);
      float2 af = up2(acc[i][1]);
      float2 ag = up2(acc[i][2]);
      float2 ao = up2(acc[i][3]);
      float gi0 = ai.x + pi.x, gi1 = ai.y + pi.y;
      float gf0 = af.x + pf.x, gf1 = af.y + pf.y;
      float gg0 = ag.x + pg.x, gg1 = ag.y + pg.y;
      float go0 = ao.x + po.x, go1 = ao.y + po.y;
      float& cj0 = (i == 0) ? c00 : c10;
      float& cj1 = (i == 0) ? c01 : c11;
      cj0 = sigf(gf0) * cj0 + sigf(gi0) * tanhf(gg0);
      cj1 = sigf(gf1) * cj1 + sigf(gi1) * tanhf(gg1);
      float h0 = sigf(go0) * tanhf(cj0);
      float h1 = sigf(go1) * tanhf(cj1);
      hh[i][0] = h0; hh[i][1] = h1;
      *reinterpret_cast<float2*>(
          &out[((size_t)tt * 64 + b) * 1024 + dir * 512 + jg]) =
          make_float2(h0, h1);
    }
    // hn[j][b]: (b0, b0+1) adjacent per j
    *reinterpret_cast<float2*>(&hn[jg * 64 + b0]) =
        make_float2(hh[0][0], hh[1][0]);
    *reinterpret_cast<float2*>(&hn[(jg + 1) * 64 + b0]) =
        make_float2(hh[0][1], hh[1][1]);

    // Grid barrier (per direction, 64 blocks) before next step reads hn.
    if (t != T - 1) {
      __threadfence();
      __syncthreads();
      if (tid == 0) {
        unsigned target = (unsigned)(t + 1);
        if (atomicAdd(&g_barcnt[dir], 1u) == NBLK_PER_DIR - 1) {
          g_barcnt[dir] = 0;
          __threadfence();
          atomicExch((unsigned*)&g_bargen[dir], target);
        } else {
          while (g_bargen[dir] < target) __nanosleep(32);
        }
      }
      __syncthreads();
    }
  }
}

// ---------------------------------------------------------------------------
// logits[b, t, tag] = out2[t*B+b, :] . fcW[tag, :] + fcb[tag]
__global__ __launch_bounds__(256)
void fc_kernel(const float* __restrict__ inp,
               const float* __restrict__ Wt,
               const float* __restrict__ bias,
               float* __restrict__ out) {
  __shared__ float rs[8][1024];
  int r0 = blockIdx.x << 3;
#pragma unroll
  for (int l = threadIdx.x; l < 2048; l += 256) {
    int r = l >> 8, f4 = (l & 255) << 2;
    *reinterpret_cast<float4*>(&rs[r][f4]) =
        *reinterpret_cast<const float4*>(&inp[(size_t)(r0 + r) * 1024 + f4]);
  }
  __syncthreads();
  int r = threadIdx.x >> 5;
  int tg = threadIdx.x & 31;
  int tag2 = tg + 32;
  bool has2 = (tag2 < TAGS);
  float a0 = 0.f, a1 = 0.f;
  for (int k = 0; k < 1024; k += 4) {
    float4 xv = *reinterpret_cast<const float4*>(&rs[r][k]);
    float4 w0 = *reinterpret_cast<const float4*>(&Wt[(size_t)tg * 1024 + k]);
    a0 += xv.x * w0.x + xv.y * w0.y + xv.z * w0.z + xv.w * w0.w;
    if (has2) {
      float4 w1 = *reinterpret_cast<const float4*>(&Wt[(size_t)tag2 * 1024 + k]);
      a1 += xv.x * w1.x + xv.y * w1.y + xv.z * w1.z + xv.w * w1.w;
    }
  }
  int row = r0 + r;
  int tq = row >> 6, bb = row & 63;
  size_t obase = ((size_t)bb * T + tq) * TAGS;
  out[obase + tg] = a0 + bias[tg];
  if (has2) out[obase + tag2] = a1 + bias[tag2];
}

// ---------------------------------------------------------------------------
extern "C" void kernel_launch(void* const* d_in, const int* in_sizes, int n_in,
                              void* d_out, int out_size) {
  const int* x = (const int*)d_in[0];
  const float* emb = (const float*)d_in[2];
  const float* Wih_f1 = (const float*)d_in[3];
  const float* Whh_f1 = (const float*)d_in[4];
  const float* bih_f1 = (const float*)d_in[5];
  const float* bhh_f1 = (const float*)d_in[6];
  const float* Wih_b1 = (const float*)d_in[7];
  const float* Whh_b1 = (const float*)d_in[8];
  const float* bih_b1 = (const float*)d_in[9];
  const float* bhh_b1 = (const float*)d_in[10];
  const float* Wih_f2 = (const float*)d_in[11];
  const float* Whh_f2 = (const float*)d_in[12];
  const float* bih_f2 = (const float*)d_in[13];
  const float* bhh_f2 = (const float*)d_in[14];
  const float* Wih_b2 = (const float*)d_in[15];
  const float* Whh_b2 = (const float*)d_in[16];
  const float* bih_b2 = (const float*)d_in[17];
  const float* bhh_b2 = (const float*)d_in[18];
  const float* fcW = (const float*)d_in[19];
  const float* fcb = (const float*)d_in[20];
  float* out = (float*)d_out;

  float *xs, *pre_f, *pre_b, *out1, *out2;
  cudaGetSymbolAddress((void**)&xs, g_xs);
  cudaGetSymbolAddress((void**)&pre_f, g_pre_f);
  cudaGetSymbolAddress((void**)&pre_b, g_pre_b);
  cudaGetSymbolAddress((void**)&out1, g_out1);
  cudaGetSymbolAddress((void**)&out2, g_out2);

  static bool attr_set = false;
  if (!attr_set) {
    cudaFuncSetAttribute(lstm_persistent,
                         cudaFuncAttributeMaxDynamicSharedMemorySize, 65536);
    attr_set = true;
  }

  embed_kernel<<<M, 128>>>(x, emb);

  dim3 gg(G / 128, M / 128);      // (16, 128)

  // Layer 1
  init_layer_kernel<<<(4 * H * B + 255) / 256, 256>>>();
  sgemm_bias_kernel<E><<<gg, 256>>>(xs, Wih_f1, bih_f1, bhh_f1, pre_f);
  sgemm_bias_kernel<E><<<gg, 256>>>(xs, Wih_b1, bih_b1, bhh_b1, pre_b);
  lstm_persistent<<<2 * NBLK_PER_DIR, 128, 65536>>>(pre_f, pre_b,
                                                    Whh_f1, Whh_b1, out1);

  // Layer 2
  init_layer_kernel<<<(4 * H * B + 255) / 256, 256>>>();
  sgemm_bias_kernel<2 * H><<<gg, 256>>>(out1, Wih_f2, bih_f2, bhh_f2, pre_f);
  sgemm_bias_kernel<2 * H><<<gg, 256>>>(out1, Wih_b2, bih_b2, bhh_b2, pre_b);
  lstm_persistent<<<2 * NBLK_PER_DIR, 128, 65536>>>(pre_f, pre_b,
                                                    Whh_f2, Whh_b2, out2);

  fc_kernel<<<M / 8, 256>>>(out2, fcW, fcb, out);
}

// round 4
// speedup vs baseline: 2.0282x; 2.0282x over previous
#include <cuda_runtime.h>
#include <math.h>

// Problem constants
namespace {
constexpr int B = 64, T = 256, E = 512, H = 512, TAGS = 50;
constexpr int G = 4 * H;   // 2048 (gate dim)
constexpr int M = T * B;   // 16384 rows
constexpr int NBLK_PER_DIR = 64;   // persistent blocks per direction
}

// Scratch (static device arrays — no cudaMalloc allowed)
__device__ float g_xs[M * E];        //  32 MB  embedded inputs [T*B, E]
__device__ float g_pre_f[M * G];     // 128 MB  x@Wih^T + biases (fwd)
__device__ float g_pre_b[M * G];     // 128 MB  (bwd)
__device__ float g_out1[M * 2 * H];  //  64 MB  layer-1 output [T*B, 2H]
__device__ float g_out2[M * 2 * H];  //  64 MB  layer-2 output
__device__ float g_hT[2][2][H * B];  // h double buffer, TRANSPOSED [parity][dir][j][b]
__device__ unsigned g_barcnt[2];               // per-dir barrier arrival counter
__device__ volatile unsigned g_bargen[2];      // per-dir barrier generation

// ---------------------------------------------------------------------------
__global__ void init_layer_kernel() {
  int i = blockIdx.x * blockDim.x + threadIdx.x;
  float* ht = &g_hT[0][0][0];
  if (i < 2 * 2 * H * B) ht[i] = 0.f;
  if (i < 2) { g_barcnt[i] = 0; g_bargen[i] = 0; }
}

// Embedding gather: g_xs[(t*B+b)*E + :] = emb[x[b,t], :]
__global__ void embed_kernel(const int* __restrict__ x,
                             const float* __restrict__ emb) {
  int row = blockIdx.x;        // t*B + b
  int t = row >> 6;
  int b = row & 63;
  int tok = x[b * T + t];
  const float4* src = reinterpret_cast<const float4*>(emb + (size_t)tok * E);
  float4* dst = reinterpret_cast<float4*>(g_xs + (size_t)row * E);
  dst[threadIdx.x] = src[threadIdx.x];   // 128 threads * float4 = 512 floats
}

// ---------------------------------------------------------------------------
// C[M, 2048] = A[M, K] @ W[2048, K]^T + (b1 + b2)
template <int K>
__global__ __launch_bounds__(256)
void sgemm_bias_kernel(const float* __restrict__ A,
                       const float* __restrict__ W,
                       const float* __restrict__ b1,
                       const float* __restrict__ b2,
                       float* __restrict__ C) {
  __shared__ float As[8][132];
  __shared__ float Ws[8][132];
  const int bm = blockIdx.y << 7;
  const int bn = blockIdx.x << 7;
  const int tid = threadIdx.x;
  const int tm = (tid >> 4) << 3;
  const int tn = (tid & 15) << 3;
  const int lrow = tid >> 1;
  const int lc4 = (tid & 1) << 2;
  const float* Ap = A + (size_t)(bm + lrow) * K + lc4;
  const float* Wp = W + (size_t)(bn + lrow) * K + lc4;

  float acc[8][8];
#pragma unroll
  for (int i = 0; i < 8; i++)
#pragma unroll
    for (int j = 0; j < 8; j++) acc[i][j] = 0.f;

  float4 av = *reinterpret_cast<const float4*>(Ap);
  float4 wv = *reinterpret_cast<const float4*>(Wp);

  for (int k0 = 0; k0 < K; k0 += 8) {
    __syncthreads();
    As[lc4 + 0][lrow] = av.x; As[lc4 + 1][lrow] = av.y;
    As[lc4 + 2][lrow] = av.z; As[lc4 + 3][lrow] = av.w;
    Ws[lc4 + 0][lrow] = wv.x; Ws[lc4 + 1][lrow] = wv.y;
    Ws[lc4 + 2][lrow] = wv.z; Ws[lc4 + 3][lrow] = wv.w;
    __syncthreads();
    if (k0 + 8 < K) {
      av = *reinterpret_cast<const float4*>(Ap + k0 + 8);
      wv = *reinterpret_cast<const float4*>(Wp + k0 + 8);
    }
#pragma unroll
    for (int kk = 0; kk < 8; kk++) {
      float ra[8], rw[8];
      *reinterpret_cast<float4*>(&ra[0]) = *reinterpret_cast<const float4*>(&As[kk][tm]);
      *reinterpret_cast<float4*>(&ra[4]) = *reinterpret_cast<const float4*>(&As[kk][tm + 4]);
      *reinterpret_cast<float4*>(&rw[0]) = *reinterpret_cast<const float4*>(&Ws[kk][tn]);
      *reinterpret_cast<float4*>(&rw[4]) = *reinterpret_cast<const float4*>(&Ws[kk][tn + 4]);
#pragma unroll
      for (int i = 0; i < 8; i++)
#pragma unroll
        for (int j = 0; j < 8; j++) acc[i][j] = fmaf(ra[i], rw[j], acc[i][j]);
    }
  }

  float bb[8];
#pragma unroll
  for (int j = 0; j < 8; j++) {
    int col = bn + tn + j;
    bb[j] = b1[col] + b2[col];
  }
#pragma unroll
  for (int i = 0; i < 8; i++) {
    size_t crow = (size_t)(bm + tm + i) * G + (bn + tn);
    float4 v0 = make_float4(acc[i][0] + bb[0], acc[i][1] + bb[1],
                            acc[i][2] + bb[2], acc[i][3] + bb[3]);
    float4 v1 = make_float4(acc[i][4] + bb[4], acc[i][5] + bb[5],
                            acc[i][6] + bb[6], acc[i][7] + bb[7]);
    *reinterpret_cast<float4*>(&C[crow]) = v0;
    *reinterpret_cast<float4*>(&C[crow + 4]) = v1;
  }
}

// ---------------------------------------------------------------------------
__device__ __forceinline__ float sigf(float x) {
  return 1.f / (1.f + __expf(-x));
}
// Packed fp32x2 FMA (Blackwell FFMA2): d = a * b + d, lanes (lo, hi).
__device__ __forceinline__ void fma2(unsigned long long& d,
                                     unsigned long long a,
                                     unsigned long long b) {
  asm("fma.rn.f32x2 %0, %1, %2, %0;" : "+l"(d) : "l"(a), "l"(b));
}
__device__ __forceinline__ unsigned long long dup2(float x) {
  unsigned long long r;
  asm("mov.b64 %0, {%1, %1};" : "=l"(r) : "f"(x));
  return r;
}
__device__ __forceinline__ float2 up2(unsigned long long v) {
  float2 r;
  asm("mov.b64 {%0, %1}, %2;" : "=f"(r.x), "=f"(r.y) : "l"(v));
  return r;
}

// Persistent BiLSTM recurrence for one layer.
// Grid: 128 blocks (dir = bx>>6, j-tile = bx&63, 8 hidden units each).
// 256 threads, split-K: warps 0-3 do k in [0,256), warps 4-7 k in [256,512).
// Each step: (1) stage full h (512x64 fp32 = 128KB) into smem with coalesced
// __ldcg float4 loads (high MLP -> latency hidden), (2) fma2 inner loop reads
// w + h from smem only, (3) split-K reduce through smem, (4) epilogue by the
// 128 low threads (c state in their registers), (5) per-dir grid barrier.
__global__ __launch_bounds__(256, 1)
void lstm_persistent(const float* __restrict__ pre_f,
                     const float* __restrict__ pre_b,
                     const float* __restrict__ Whh_f,
                     const float* __restrict__ Whh_b,
                     float* __restrict__ out) {
  extern __shared__ float smem[];
  float* w_s = smem;              // [512][32]  = 64 KB
  float* h_s = smem + 512 * 32;   // [512][64]  = 128 KB (reused as red buffer)

  const int dir = blockIdx.x >> 6;
  const int jt = blockIdx.x & 63;
  const int jblk = jt << 3;
  const int tid = threadIdx.x;
  const int lane = tid & 31;
  const int warp = tid >> 5;
  const int kh = warp >> 2;                   // 0/1 k-half
  const int wl = warp & 3;
  const int jp = lane >> 3;                   // 0..3 j-pair
  const int bpg = (wl << 3) + (lane & 7);     // 0..31 batch pair
  const int b0 = bpg << 1;
  const int jg = jblk + (jp << 1);
  const int kbase = kh << 8;
  const float* Whh = dir ? Whh_b : Whh_f;
  const float* pre = dir ? pre_b : pre_f;

  // Stage Whh slice once: w_s[k*32 + jp*8 + g*2 + jh] = Whh[g*512+jblk+jl][k]
  for (int e = tid; e < 4096; e += 256) {
    int rl = e & 31;                 // local row: g = rl>>3, jl = rl&7
    int k4 = (e >> 5) << 2;
    int g = rl >> 3, jl = rl & 7;
    float4 v = *reinterpret_cast<const float4*>(
        &Whh[((size_t)(g * 512 + jblk + jl)) * 512 + k4]);
    int col = ((jl >> 1) << 3) + (g << 1) + (jl & 1);
    w_s[(k4 + 0) * 32 + col] = v.x;
    w_s[(k4 + 1) * 32 + col] = v.y;
    w_s[(k4 + 2) * 32 + col] = v.z;
    w_s[(k4 + 3) * 32 + col] = v.w;
  }

  float c00 = 0.f, c01 = 0.f, c10 = 0.f, c11 = 0.f;  // [bhalf][jhalf] (low tids)
  const float* wbase = w_s + (jp << 3);
  unsigned long long* red = reinterpret_cast<unsigned long long*>(h_s);

  for (int t = 0; t < T; t++) {
    const int tt = dir ? (T - 1 - t) : t;
    const float* hp = g_hT[t & 1][dir];
    float* hn = g_hT[(t & 1) ^ 1][dir];

    __syncthreads();   // protect h_s/red reuse across iterations
    // Stage full h[512][64] into smem, coalesced, L1-bypassing.
    {
      const float4* src = reinterpret_cast<const float4*>(hp);
      float4* dst = reinterpret_cast<float4*>(h_s);
#pragma unroll
      for (int i = 0; i < 32; i++) {
        int idx = tid + (i << 8);
        dst[idx] = __ldcg(src + idx);
      }
    }
    __syncthreads();

    unsigned long long acc[2][4];   // [bhalf][gate], lanes = (j0, j1)
#pragma unroll
    for (int i = 0; i < 2; i++)
#pragma unroll
      for (int g = 0; g < 4; g++) acc[i][g] = 0ull;

    const float* hb = h_s + b0;
#pragma unroll 8
    for (int k = kbase; k < kbase + 256; k++) {
      const ulonglong2* wk =
          reinterpret_cast<const ulonglong2*>(wbase + k * 32);
      ulonglong2 wA = wk[0];   // (gate0 jpair, gate1 jpair)
      ulonglong2 wB = wk[1];   // (gate2 jpair, gate3 jpair)
      float2 hv = *reinterpret_cast<const float2*>(hb + k * 64);
      unsigned long long h0 = dup2(hv.x);
      unsigned long long h1 = dup2(hv.y);
      fma2(acc[0][0], wA.x, h0); fma2(acc[1][0], wA.x, h1);
      fma2(acc[0][1], wA.y, h0); fma2(acc[1][1], wA.y, h1);
      fma2(acc[0][2], wB.x, h0); fma2(acc[1][2], wB.x, h1);
      fma2(acc[0][3], wB.y, h0); fma2(acc[1][3], wB.y, h1);
    }

    __syncthreads();   // all reads of h_s done before red writes
    if (kh == 1) {     // upper k-half dumps accumulators (bank-interleaved)
      int base = tid - 128;
#pragma unroll
      for (int i = 0; i < 2; i++)
#pragma unroll
        for (int g = 0; g < 4; g++)
          red[(i * 4 + g) * 128 + base] = acc[i][g];
    }
    __syncthreads();

    if (kh == 0) {
      // Combine halves + epilogue for (j0,j1) x (b0,b0+1)
      float hh[2][2];
#pragma unroll
      for (int i = 0; i < 2; i++) {
        int b = b0 + i;
        float2 a0 = up2(acc[i][0]), r0 = up2(red[(i * 4 + 0) * 128 + tid]);
        float2 a1 = up2(acc[i][1]), r1 = up2(red[(i * 4 + 1) * 128 + tid]);
        float2 a2 = up2(acc[i][2]), r2 = up2(red[(i * 4 + 2) * 128 + tid]);
        float2 a3 = up2(acc[i][3]), r3 = up2(red[(i * 4 + 3) * 128 + tid]);
        const float* pp = pre + ((size_t)tt * 64 + b) * 2048 + jg;
        float2 pi = *reinterpret_cast<const float2*>(pp);
        float2 pf = *reinterpret_cast<const float2*>(pp + 512);
        float2 pg = *reinterpret_cast<const float2*>(pp + 1024);
        float2 po = *reinterpret_cast<const float2*>(pp + 1536);
        float gi0 = a0.x + r0.x + pi.x, gi1 = a0.y + r0.y + pi.y;
        float gf0 = a1.x + r1.x + pf.x, gf1 = a1.y + r1.y + pf.y;
        float gg0 = a2.x + r2.x + pg.x, gg1 = a2.y + r2.y + pg.y;
        float go0 = a3.x + r3.x + po.x, go1 = a3.y + r3.y + po.y;
        float& cj0 = (i == 0) ? c00 : c10;
        float& cj1 = (i == 0) ? c01 : c11;
        cj0 = sigf(gf0) * cj0 + sigf(gi0) * tanhf(gg0);
        cj1 = sigf(gf1) * cj1 + sigf(gi1) * tanhf(gg1);
        float h0v = sigf(go0) * tanhf(cj0);
        float h1v = sigf(go1) * tanhf(cj1);
        hh[i][0] = h0v; hh[i][1] = h1v;
        *reinterpret_cast<float2*>(
            &out[((size_t)tt * 64 + b) * 1024 + dir * 512 + jg]) =
            make_float2(h0v, h1v);
      }
      *reinterpret_cast<float2*>(&hn[jg * 64 + b0]) =
          make_float2(hh[0][0], hh[1][0]);
      *reinterpret_cast<float2*>(&hn[(jg + 1) * 64 + b0]) =
          make_float2(hh[0][1], hh[1][1]);
    }

    // Grid barrier (per direction, 64 blocks) before next step reads hn.
    if (t != T - 1) {
      __threadfence();
      __syncthreads();
      if (tid == 0) {
        unsigned target = (unsigned)(t + 1);
        if (atomicAdd(&g_barcnt[dir], 1u) == NBLK_PER_DIR - 1) {
          g_barcnt[dir] = 0;
          __threadfence();
          atomicExch((unsigned*)&g_bargen[dir], target);
        } else {
          while (g_bargen[dir] < target) __nanosleep(32);
        }
      }
      __syncthreads();
    }
  }
}

// ---------------------------------------------------------------------------
// logits[b, t, tag] = out2[t*B+b, :] . fcW[tag, :] + fcb[tag]
__global__ __launch_bounds__(256)
void fc_kernel(const float* __restrict__ inp,
               const float* __restrict__ Wt,
               const float* __restrict__ bias,
               float* __restrict__ out) {
  __shared__ float rs[8][1024];
  int r0 = blockIdx.x << 3;
#pragma unroll
  for (int l = threadIdx.x; l < 2048; l += 256) {
    int r = l >> 8, f4 = (l & 255) << 2;
    *reinterpret_cast<float4*>(&rs[r][f4]) =
        *reinterpret_cast<const float4*>(&inp[(size_t)(r0 + r) * 1024 + f4]);
  }
  __syncthreads();
  int r = threadIdx.x >> 5;
  int tg = threadIdx.x & 31;
  int tag2 = tg + 32;
  bool has2 = (tag2 < TAGS);
  float a0 = 0.f, a1 = 0.f;
  for (int k = 0; k < 1024; k += 4) {
    float4 xv = *reinterpret_cast<const float4*>(&rs[r][k]);
    float4 w0 = *reinterpret_cast<const float4*>(&Wt[(size_t)tg * 1024 + k]);
    a0 += xv.x * w0.x + xv.y * w0.y + xv.z * w0.z + xv.w * w0.w;
    if (has2) {
      float4 w1 = *reinterpret_cast<const float4*>(&Wt[(size_t)tag2 * 1024 + k]);
      a1 += xv.x * w1.x + xv.y * w1.y + xv.z * w1.z + xv.w * w1.w;
    }
  }
  int row = r0 + r;
  int tq = row >> 6, bb = row & 63;
  size_t obase = ((size_t)bb * T + tq) * TAGS;
  out[obase + tg] = a0 + bias[tg];
  if (has2) out[obase + tag2] = a1 + bias[tag2];
}

// ---------------------------------------------------------------------------
extern "C" void kernel_launch(void* const* d_in, const int* in_sizes, int n_in,
                              void* d_out, int out_size) {
  const int* x = (const int*)d_in[0];
  const float* emb = (const float*)d_in[2];
  const float* Wih_f1 = (const float*)d_in[3];
  const float* Whh_f1 = (const float*)d_in[4];
  const float* bih_f1 = (const float*)d_in[5];
  const float* bhh_f1 = (const float*)d_in[6];
  const float* Wih_b1 = (const float*)d_in[7];
  const float* Whh_b1 = (const float*)d_in[8];
  const float* bih_b1 = (const float*)d_in[9];
  const float* bhh_b1 = (const float*)d_in[10];
  const float* Wih_f2 = (const float*)d_in[11];
  const float* Whh_f2 = (const float*)d_in[12];
  const float* bih_f2 = (const float*)d_in[13];
  const float* bhh_f2 = (const float*)d_in[14];
  const float* Wih_b2 = (const float*)d_in[15];
  const float* Whh_b2 = (const float*)d_in[16];
  const float* bih_b2 = (const float*)d_in[17];
  const float* bhh_b2 = (const float*)d_in[18];
  const float* fcW = (const float*)d_in[19];
  const float* fcb = (const float*)d_in[20];
  float* out = (float*)d_out;

  float *xs, *pre_f, *pre_b, *out1, *out2;
  cudaGetSymbolAddress((void**)&xs, g_xs);
  cudaGetSymbolAddress((void**)&pre_f, g_pre_f);
  cudaGetSymbolAddress((void**)&pre_b, g_pre_b);
  cudaGetSymbolAddress((void**)&out1, g_out1);
  cudaGetSymbolAddress((void**)&out2, g_out2);

  constexpr int LSTM_SMEM = (512 * 32 + 512 * 64) * 4;   // 192 KB
  static bool attr_set = false;
  if (!attr_set) {
    cudaFuncSetAttribute(lstm_persistent,
                         cudaFuncAttributeMaxDynamicSharedMemorySize, LSTM_SMEM);
    attr_set = true;
  }

  embed_kernel<<<M, 128>>>(x, emb);

  dim3 gg(G / 128, M / 128);      // (16, 128)

  // Layer 1
  init_layer_kernel<<<(4 * H * B + 255) / 256, 256>>>();
  sgemm_bias_kernel<E><<<gg, 256>>>(xs, Wih_f1, bih_f1, bhh_f1, pre_f);
  sgemm_bias_kernel<E><<<gg, 256>>>(xs, Wih_b1, bih_b1, bhh_b1, pre_b);
  lstm_persistent<<<2 * NBLK_PER_DIR, 256, LSTM_SMEM>>>(pre_f, pre_b,
                                                        Whh_f1, Whh_b1, out1);

  // Layer 2
  init_layer_kernel<<<(4 * H * B + 255) / 256, 256>>>();
  sgemm_bias_kernel<2 * H><<<gg, 256>>>(out1, Wih_f2, bih_f2, bhh_f2, pre_f);
  sgemm_bias_kernel<2 * H><<<gg, 256>>>(out1, Wih_b2, bih_b2, bhh_b2, pre_b);
  lstm_persistent<<<2 * NBLK_PER_DIR, 256, LSTM_SMEM>>>(pre_f, pre_b,
                                                        Whh_f2, Whh_b2, out2);

  fc_kernel<<<M / 8, 256>>>(out2, fcW, fcb, out);
}

// round 5
// speedup vs baseline: 2.0914x; 1.0312x over previous
#include <cuda_runtime.h>
#include <math.h>

// Problem constants
namespace {
constexpr int B = 64, T = 256, E = 512, H = 512, TAGS = 50;
constexpr int G = 4 * H;   // 2048 (gate dim)
constexpr int M = T * B;   // 16384 rows
constexpr int NBLK_PER_DIR = 64;   // persistent blocks per direction
}

// Scratch (static device arrays — no cudaMalloc allowed)
__device__ float g_xs[M * E];        //  32 MB  embedded inputs [T*B, E]
__device__ float g_pre_f[M * G];     // 128 MB  x@Wih^T + biases (fwd)
__device__ float g_pre_b[M * G];     // 128 MB  (bwd)
__device__ float g_out1[M * 2 * H];  //  64 MB  layer-1 output [T*B, 2H]
__device__ float g_out2[M * 2 * H];  //  64 MB  layer-2 output
__device__ float g_hT[2][2][H * B];  // h double buffer, TRANSPOSED [parity][dir][j][b]
__device__ unsigned g_barcnt[2];               // per-dir barrier arrival counter
__device__ volatile unsigned g_bargen[2];      // per-dir barrier generation

// ---------------------------------------------------------------------------
__global__ void init_layer_kernel() {
  int i = blockIdx.x * blockDim.x + threadIdx.x;
  float* ht = &g_hT[0][0][0];
  if (i < 2 * 2 * H * B) ht[i] = 0.f;
  if (i < 2) { g_barcnt[i] = 0; g_bargen[i] = 0; }
}

// Embedding gather: g_xs[(t*B+b)*E + :] = emb[x[b,t], :]
__global__ void embed_kernel(const int* __restrict__ x,
                             const float* __restrict__ emb) {
  int row = blockIdx.x;        // t*B + b
  int t = row >> 6;
  int b = row & 63;
  int tok = x[b * T + t];
  const float4* src = reinterpret_cast<const float4*>(emb + (size_t)tok * E);
  float4* dst = reinterpret_cast<float4*>(g_xs + (size_t)row * E);
  dst[threadIdx.x] = src[threadIdx.x];   // 128 threads * float4 = 512 floats
}

// ---------------------------------------------------------------------------
// Packed fp32x2 FMA (Blackwell FFMA2): d = a * b + d, lanes (lo, hi).
__device__ __forceinline__ void fma2(unsigned long long& d,
                                     unsigned long long a,
                                     unsigned long long b) {
  asm("fma.rn.f32x2 %0, %1, %2, %0;" : "+l"(d) : "l"(a), "l"(b));
}
__device__ __forceinline__ unsigned long long dup2(float x) {
  unsigned long long r;
  asm("mov.b64 %0, {%1, %1};" : "=l"(r) : "f"(x));
  return r;
}
__device__ __forceinline__ float2 up2(unsigned long long v) {
  float2 r;
  asm("mov.b64 {%0, %1}, %2;" : "=f"(r.x), "=f"(r.y) : "l"(v));
  return r;
}
__device__ __forceinline__ void cp_async16(unsigned smem_addr,
                                           const void* gptr) {
  asm volatile("cp.async.cg.shared.global [%0], [%1], 16;"
               :: "r"(smem_addr), "l"(gptr));
}
__device__ __forceinline__ void cp_commit() {
  asm volatile("cp.async.commit_group;" ::: "memory");
}
template <int N>
__device__ __forceinline__ void cp_wait() {
  asm volatile("cp.async.wait_group %0;" :: "n"(N) : "memory");
}

// ---------------------------------------------------------------------------
// C[M, 2048] = A[M, K] @ W[2048, K]^T + (b1 + b2), FFMA2 inner product.
template <int K>
__global__ __launch_bounds__(256)
void sgemm_bias_kernel(const float* __restrict__ A,
                       const float* __restrict__ W,
                       const float* __restrict__ b1,
                       const float* __restrict__ b2,
                       float* __restrict__ C) {
  __shared__ float As[8][132];
  __shared__ float Ws[8][132];
  const int bm = blockIdx.y << 7;
  const int bn = blockIdx.x << 7;
  const int tid = threadIdx.x;
  const int tm = (tid >> 4) << 3;
  const int tn = (tid & 15) << 3;
  const int lrow = tid >> 1;
  const int lc4 = (tid & 1) << 2;
  const float* Ap = A + (size_t)(bm + lrow) * K + lc4;
  const float* Wp = W + (size_t)(bn + lrow) * K + lc4;

  unsigned long long accp[8][4];   // [i][jp], lanes = (n0, n1)
#pragma unroll
  for (int i = 0; i < 8; i++)
#pragma unroll
    for (int jp = 0; jp < 4; jp++) accp[i][jp] = 0ull;

  float4 av = *reinterpret_cast<const float4*>(Ap);
  float4 wv = *reinterpret_cast<const float4*>(Wp);

  for (int k0 = 0; k0 < K; k0 += 8) {
    __syncthreads();
    As[lc4 + 0][lrow] = av.x; As[lc4 + 1][lrow] = av.y;
    As[lc4 + 2][lrow] = av.z; As[lc4 + 3][lrow] = av.w;
    Ws[lc4 + 0][lrow] = wv.x; Ws[lc4 + 1][lrow] = wv.y;
    Ws[lc4 + 2][lrow] = wv.z; Ws[lc4 + 3][lrow] = wv.w;
    __syncthreads();
    if (k0 + 8 < K) {
      av = *reinterpret_cast<const float4*>(Ap + k0 + 8);
      wv = *reinterpret_cast<const float4*>(Wp + k0 + 8);
    }
#pragma unroll
    for (int kk = 0; kk < 8; kk++) {
      float4 ra0 = *reinterpret_cast<const float4*>(&As[kk][tm]);
      float4 ra1 = *reinterpret_cast<const float4*>(&As[kk][tm + 4]);
      ulonglong2 w0 = *reinterpret_cast<const ulonglong2*>(&Ws[kk][tn]);
      ulonglong2 w1 = *reinterpret_cast<const ulonglong2*>(&Ws[kk][tn + 4]);
      unsigned long long ha[8];
      ha[0] = dup2(ra0.x); ha[1] = dup2(ra0.y);
      ha[2] = dup2(ra0.z); ha[3] = dup2(ra0.w);
      ha[4] = dup2(ra1.x); ha[5] = dup2(ra1.y);
      ha[6] = dup2(ra1.z); ha[7] = dup2(ra1.w);
#pragma unroll
      for (int i = 0; i < 8; i++) {
        fma2(accp[i][0], w0.x, ha[i]);
        fma2(accp[i][1], w0.y, ha[i]);
        fma2(accp[i][2], w1.x, ha[i]);
        fma2(accp[i][3], w1.y, ha[i]);
      }
    }
  }

  float bb[8];
#pragma unroll
  for (int j = 0; j < 8; j++) {
    int col = bn + tn + j;
    bb[j] = b1[col] + b2[col];
  }
#pragma unroll
  for (int i = 0; i < 8; i++) {
    float2 p0 = up2(accp[i][0]);
    float2 p1 = up2(accp[i][1]);
    float2 p2 = up2(accp[i][2]);
    float2 p3 = up2(accp[i][3]);
    size_t crow = (size_t)(bm + tm + i) * G + (bn + tn);
    float4 v0 = make_float4(p0.x + bb[0], p0.y + bb[1],
                            p1.x + bb[2], p1.y + bb[3]);
    float4 v1 = make_float4(p2.x + bb[4], p2.y + bb[5],
                            p3.x + bb[6], p3.y + bb[7]);
    *reinterpret_cast<float4*>(&C[crow]) = v0;
    *reinterpret_cast<float4*>(&C[crow + 4]) = v1;
  }
}

// ---------------------------------------------------------------------------
__device__ __forceinline__ float sigf(float x) {
  return 1.f / (1.f + __expf(-x));
}

// Persistent BiLSTM recurrence for one layer.
// Grid: 128 blocks (dir = bx>>6, j-tile = bx&63, 8 hidden units each).
// 256 threads, split-K (warp group kh handles half of each 256-k chunk).
// Each step: issue cp.async for BOTH 64KB h chunks up-front (2 groups),
// wait_group 1 -> compute chunk0 while chunk1 is still arriving,
// wait_group 0 -> compute chunk1. Split-K reduce through smem, epilogue by
// the 128 low threads (c state in their registers), per-dir grid barrier.
__global__ __launch_bounds__(256, 1)
void lstm_persistent(const float* __restrict__ pre_f,
                     const float* __restrict__ pre_b,
                     const float* __restrict__ Whh_f,
                     const float* __restrict__ Whh_b,
                     float* __restrict__ out) {
  extern __shared__ float smem[];
  float* w_s = smem;              // [512][32]  = 64 KB
  float* h_s = smem + 512 * 32;   // [512][64]  = 128 KB (reused as red buffer)

  const int dir = blockIdx.x >> 6;
  const int jt = blockIdx.x & 63;
  const int jblk = jt << 3;
  const int tid = threadIdx.x;
  const int lane = tid & 31;
  const int warp = tid >> 5;
  const int kh = warp >> 2;                   // 0/1 split-K half
  const int wl = warp & 3;
  const int jp = lane >> 3;                   // 0..3 j-pair
  const int bpg = (wl << 3) + (lane & 7);     // 0..31 batch pair
  const int b0 = bpg << 1;
  const int jg = jblk + (jp << 1);
  const float* Whh = dir ? Whh_b : Whh_f;
  const float* pre = dir ? pre_b : pre_f;

  // Stage Whh slice once: w_s[k*32 + jp*8 + g*2 + jh] = Whh[g*512+jblk+jl][k]
  for (int e = tid; e < 4096; e += 256) {
    int rl = e & 31;                 // local row: g = rl>>3, jl = rl&7
    int k4 = (e >> 5) << 2;
    int g = rl >> 3, jl = rl & 7;
    float4 v = *reinterpret_cast<const float4*>(
        &Whh[((size_t)(g * 512 + jblk + jl)) * 512 + k4]);
    int col = ((jl >> 1) << 3) + (g << 1) + (jl & 1);
    w_s[(k4 + 0) * 32 + col] = v.x;
    w_s[(k4 + 1) * 32 + col] = v.y;
    w_s[(k4 + 2) * 32 + col] = v.z;
    w_s[(k4 + 3) * 32 + col] = v.w;
  }

  float c00 = 0.f, c01 = 0.f, c10 = 0.f, c11 = 0.f;  // [bhalf][jhalf] (low tids)
  const float* wbase = w_s + (jp << 3);
  const float* hb = h_s + b0;
  unsigned long long* red = reinterpret_cast<unsigned long long*>(h_s);
  const unsigned h_s_sa =
      static_cast<unsigned>(__cvta_generic_to_shared(h_s));

  for (int t = 0; t < T; t++) {
    const int tt = dir ? (T - 1 - t) : t;
    const float* hp = g_hT[t & 1][dir];
    float* hn = g_hT[(t & 1) ^ 1][dir];

    __syncthreads();   // h_s/red free (prev epilogue done)

    // Issue async stage of full h[512][64]: 2 groups of 64KB each.
    {
      const float4* src = reinterpret_cast<const float4*>(hp);
#pragma unroll
      for (int i = 0; i < 16; i++) {
        int idx = tid + (i << 8);
        cp_async16(h_s_sa + idx * 16, src + idx);
      }
      cp_commit();
#pragma unroll
      for (int i = 16; i < 32; i++) {
        int idx = tid + (i << 8);
        cp_async16(h_s_sa + idx * 16, src + idx);
      }
      cp_commit();
    }

    unsigned long long acc[2][4];   // [bhalf][gate], lanes = (j0, j1)
#pragma unroll
    for (int i = 0; i < 2; i++)
#pragma unroll
      for (int g = 0; g < 4; g++) acc[i][g] = 0ull;

    cp_wait<1>();      // chunk0 (k < 256) in smem
    __syncthreads();

#pragma unroll
    for (int chunk = 0; chunk < 2; chunk++) {
      const int kb = (chunk << 8) + (kh << 7);
#pragma unroll 8
      for (int k = kb; k < kb + 128; k++) {
        const ulonglong2* wk =
            reinterpret_cast<const ulonglong2*>(wbase + k * 32);
        ulonglong2 wA = wk[0];   // (gate0 jpair, gate1 jpair)
        ulonglong2 wB = wk[1];   // (gate2 jpair, gate3 jpair)
        float2 hv = *reinterpret_cast<const float2*>(hb + k * 64);
        unsigned long long h0 = dup2(hv.x);
        unsigned long long h1 = dup2(hv.y);
        fma2(acc[0][0], wA.x, h0); fma2(acc[1][0], wA.x, h1);
        fma2(acc[0][1], wA.y, h0); fma2(acc[1][1], wA.y, h1);
        fma2(acc[0][2], wB.x, h0); fma2(acc[1][2], wB.x, h1);
        fma2(acc[0][3], wB.y, h0); fma2(acc[1][3], wB.y, h1);
      }
      if (chunk == 0) {
        cp_wait<0>();  // chunk1 (k >= 256) in smem; overlapped with compute
        __syncthreads();
      }
    }

    __syncthreads();   // all reads of h_s done before red writes
    if (kh == 1) {     // upper split-K half dumps accumulators
      int base = tid - 128;
#pragma unroll
      for (int i = 0; i < 2; i++)
#pragma unroll
        for (int g = 0; g < 4; g++)
          red[(i * 4 + g) * 128 + base] = acc[i][g];
    }
    __syncthreads();

    if (kh == 0) {
      // Combine halves + epilogue for (j0,j1) x (b0,b0+1)
      float hh[2][2];
#pragma unroll
      for (int i = 0; i < 2; i++) {
        int b = b0 + i;
        float2 a0 = up2(acc[i][0]), r0 = up2(red[(i * 4 + 0) * 128 + tid]);
        float2 a1 = up2(acc[i][1]), r1 = up2(red[(i * 4 + 1) * 128 + tid]);
        float2 a2 = up2(acc[i][2]), r2 = up2(red[(i * 4 + 2) * 128 + tid]);
        float2 a3 = up2(acc[i][3]), r3 = up2(red[(i * 4 + 3) * 128 + tid]);
        const float* pp = pre + ((size_t)tt * 64 + b) * 2048 + jg;
        float2 pi = *reinterpret_cast<const float2*>(pp);
        float2 pf = *reinterpret_cast<const float2*>(pp + 512);
        float2 pg = *reinterpret_cast<const float2*>(pp + 1024);
        float2 po = *reinterpret_cast<const float2*>(pp + 1536);
        float gi0 = a0.x + r0.x + pi.x, gi1 = a0.y + r0.y + pi.y;
        float gf0 = a1.x + r1.x + pf.x, gf1 = a1.y + r1.y + pf.y;
        float gg0 = a2.x + r2.x + pg.x, gg1 = a2.y + r2.y + pg.y;
        float go0 = a3.x + r3.x + po.x, go1 = a3.y + r3.y + po.y;
        float& cj0 = (i == 0) ? c00 : c10;
        float& cj1 = (i == 0) ? c01 : c11;
        cj0 = sigf(gf0) * cj0 + sigf(gi0) * tanhf(gg0);
        cj1 = sigf(gf1) * cj1 + sigf(gi1) * tanhf(gg1);
        float h0v = sigf(go0) * tanhf(cj0);
        float h1v = sigf(go1) * tanhf(cj1);
        hh[i][0] = h0v; hh[i][1] = h1v;
        *reinterpret_cast<float2*>(
            &out[((size_t)tt * 64 + b) * 1024 + dir * 512 + jg]) =
            make_float2(h0v, h1v);
      }
      *reinterpret_cast<float2*>(&hn[jg * 64 + b0]) =
          make_float2(hh[0][0], hh[1][0]);
      *reinterpret_cast<float2*>(&hn[(jg + 1) * 64 + b0]) =
          make_float2(hh[0][1], hh[1][1]);
    }

    // Grid barrier (per direction, 64 blocks) before next step reads hn.
    if (t != T - 1) {
      __threadfence();
      __syncthreads();
      if (tid == 0) {
        unsigned target = (unsigned)(t + 1);
        if (atomicAdd(&g_barcnt[dir], 1u) == NBLK_PER_DIR - 1) {
          g_barcnt[dir] = 0;
          __threadfence();
          atomicExch((unsigned*)&g_bargen[dir], target);
        } else {
          while (g_bargen[dir] < target) __nanosleep(32);
        }
      }
      __syncthreads();
    }
  }
}

// ---------------------------------------------------------------------------
// logits[b, t, tag] = out2[t*B+b, :] . fcW[tag, :] + fcb[tag]
__global__ __launch_bounds__(256)
void fc_kernel(const float* __restrict__ inp,
               const float* __restrict__ Wt,
               const float* __restrict__ bias,
               float* __restrict__ out) {
  __shared__ float rs[8][1024];
  int r0 = blockIdx.x << 3;
#pragma unroll
  for (int l = threadIdx.x; l < 2048; l += 256) {
    int r = l >> 8, f4 = (l & 255) << 2;
    *reinterpret_cast<float4*>(&rs[r][f4]) =
        *reinterpret_cast<const float4*>(&inp[(size_t)(r0 + r) * 1024 + f4]);
  }
  __syncthreads();
  int r = threadIdx.x >> 5;
  int tg = threadIdx.x & 31;
  int tag2 = tg + 32;
  bool has2 = (tag2 < TAGS);
  float a0 = 0.f, a1 = 0.f;
  for (int k = 0; k < 1024; k += 4) {
    float4 xv = *reinterpret_cast<const float4*>(&rs[r][k]);
    float4 w0 = *reinterpret_cast<const float4*>(&Wt[(size_t)tg * 1024 + k]);
    a0 += xv.x * w0.x + xv.y * w0.y + xv.z * w0.z + xv.w * w0.w;
    if (has2) {
      float4 w1 = *reinterpret_cast<const float4*>(&Wt[(size_t)tag2 * 1024 + k]);
      a1 += xv.x * w1.x + xv.y * w1.y + xv.z * w1.z + xv.w * w1.w;
    }
  }
  int row = r0 + r;
  int tq = row >> 6, bb = row & 63;
  size_t obase = ((size_t)bb * T + tq) * TAGS;
  out[obase + tg] = a0 + bias[tg];
  if (has2) out[obase + tag2] = a1 + bias[tag2];
}

// ---------------------------------------------------------------------------
extern "C" void kernel_launch(void* const* d_in, const int* in_sizes, int n_in,
                              void* d_out, int out_size) {
  const int* x = (const int*)d_in[0];
  const float* emb = (const float*)d_in[2];
  const float* Wih_f1 = (const float*)d_in[3];
  const float* Whh_f1 = (const float*)d_in[4];
  const float* bih_f1 = (const float*)d_in[5];
  const float* bhh_f1 = (const float*)d_in[6];
  const float* Wih_b1 = (const float*)d_in[7];
  const float* Whh_b1 = (const float*)d_in[8];
  const float* bih_b1 = (const float*)d_in[9];
  const float* bhh_b1 = (const float*)d_in[10];
  const float* Wih_f2 = (const float*)d_in[11];
  const float* Whh_f2 = (const float*)d_in[12];
  const float* bih_f2 = (const float*)d_in[13];
  const float* bhh_f2 = (const float*)d_in[14];
  const float* Wih_b2 = (const float*)d_in[15];
  const float* Whh_b2 = (const float*)d_in[16];
  const float* bih_b2 = (const float*)d_in[17];
  const float* bhh_b2 = (const float*)d_in[18];
  const float* fcW = (const float*)d_in[19];
  const float* fcb = (const float*)d_in[20];
  float* out = (float*)d_out;

  float *xs, *pre_f, *pre_b, *out1, *out2;
  cudaGetSymbolAddress((void**)&xs, g_xs);
  cudaGetSymbolAddress((void**)&pre_f, g_pre_f);
  cudaGetSymbolAddress((void**)&pre_b, g_pre_b);
  cudaGetSymbolAddress((void**)&out1, g_out1);
  cudaGetSymbolAddress((void**)&out2, g_out2);

  constexpr int LSTM_SMEM = (512 * 32 + 512 * 64) * 4;   // 192 KB
  static bool attr_set = false;
  if (!attr_set) {
    cudaFuncSetAttribute(lstm_persistent,
                         cudaFuncAttributeMaxDynamicSharedMemorySize, LSTM_SMEM);
    attr_set = true;
  }

  embed_kernel<<<M, 128>>>(x, emb);

  dim3 gg(G / 128, M / 128);      // (16, 128)

  // Layer 1
  init_layer_kernel<<<(4 * H * B + 255) / 256, 256>>>();
  sgemm_bias_kernel<E><<<gg, 256>>>(xs, Wih_f1, bih_f1, bhh_f1, pre_f);
  sgemm_bias_kernel<E><<<gg, 256>>>(xs, Wih_b1, bih_b1, bhh_b1, pre_b);
  lstm_persistent<<<2 * NBLK_PER_DIR, 256, LSTM_SMEM>>>(pre_f, pre_b,
                                                        Whh_f1, Whh_b1, out1);

  // Layer 2
  init_layer_kernel<<<(4 * H * B + 255) / 256, 256>>>();
  sgemm_bias_kernel<2 * H><<<gg, 256>>>(out1, Wih_f2, bih_f2, bhh_f2, pre_f);
  sgemm_bias_kernel<2 * H><<<gg, 256>>>(out1, Wih_b2, bih_b2, bhh_b2, pre_b);
  lstm_persistent<<<2 * NBLK_PER_DIR, 256, LSTM_SMEM>>>(pre_f, pre_b,
                                                        Whh_f2, Whh_b2, out2);

  fc_kernel<<<M / 8, 256>>>(out2, fcW, fcb, out);
}

// round 7
// speedup vs baseline: 2.6191x; 1.2524x over previous
#include <cuda_runtime.h>
#include <cuda_bf16.h>
#include <math.h>

// Problem constants
namespace {
constexpr int B = 64, T = 256, E = 512, H = 512, TAGS = 50;
constexpr int G = 4 * H;   // 2048 (gate dim)
constexpr int M = T * B;   // 16384 rows
constexpr int NBLK_PER_DIR = 64;   // persistent blocks per direction
}

// Scratch (static device arrays — no cudaMalloc allowed)
__device__ float g_xs[M * E];        //  32 MB  embedded inputs [T*B, E]
__device__ float g_pre_f[M * G];     // 128 MB  x@Wih^T + biases (fwd)
__device__ float g_pre_b[M * G];     // 128 MB  (bwd)
__device__ float g_out1[M * 2 * H];  //  64 MB  layer-1 output [T*B, 2H]
__device__ float g_out2[M * 2 * H];  //  64 MB  layer-2 output
__device__ float g_hT[2][2][H * B];  // h double buffer, TRANSPOSED [parity][dir][j][b]
__device__ unsigned g_barcnt[2];
__device__ volatile unsigned g_bargen[2];
// bf16 split operands for tensor-core GEMMs
__device__ __align__(256) __nv_bfloat16 g_ahi[M * 1024];       // 32 MB
__device__ __align__(256) __nv_bfloat16 g_alo[M * 1024];       // 32 MB
__device__ __align__(256) __nv_bfloat16 g_whi[G * 1024];       //  4 MB
__device__ __align__(256) __nv_bfloat16 g_wlo[G * 1024];       //  4 MB

// ---------------------------------------------------------------------------
__device__ __forceinline__ unsigned s2u32(const void* p) {
  return static_cast<unsigned>(__cvta_generic_to_shared(p));
}
__device__ __forceinline__ void cp_async16(unsigned sa, const void* g) {
  asm volatile("cp.async.cg.shared.global [%0], [%1], 16;" :: "r"(sa), "l"(g));
}
__device__ __forceinline__ void cp_commit() {
  asm volatile("cp.async.commit_group;" ::: "memory");
}
template <int N>
__device__ __forceinline__ void cp_wait() {
  asm volatile("cp.async.wait_group %0;" :: "n"(N) : "memory");
}
__device__ __forceinline__ void ldmx4(unsigned* r, unsigned addr) {
  asm volatile("ldmatrix.sync.aligned.m8n8.x4.shared.b16 {%0,%1,%2,%3}, [%4];"
               : "=r"(r[0]), "=r"(r[1]), "=r"(r[2]), "=r"(r[3]) : "r"(addr));
}
__device__ __forceinline__ void hmma(float* d, const unsigned* a,
                                     unsigned b0, unsigned b1) {
  asm volatile(
      "mma.sync.aligned.m16n8k16.row.col.f32.bf16.bf16.f32 "
      "{%0,%1,%2,%3}, {%4,%5,%6,%7}, {%8,%9}, {%0,%1,%2,%3};"
      : "+f"(d[0]), "+f"(d[1]), "+f"(d[2]), "+f"(d[3])
      : "r"(a[0]), "r"(a[1]), "r"(a[2]), "r"(a[3]), "r"(b0), "r"(b1));
}

// ---------------------------------------------------------------------------
__global__ void init_layer_kernel() {
  int i = blockIdx.x * blockDim.x + threadIdx.x;
  float* ht = &g_hT[0][0][0];
  if (i < 2 * 2 * H * B) ht[i] = 0.f;
  if (i < 2) { g_barcnt[i] = 0; g_bargen[i] = 0; }
}

// Embedding gather
__global__ void embed_kernel(const int* __restrict__ x,
                             const float* __restrict__ emb) {
  int row = blockIdx.x;
  int t = row >> 6;
  int b = row & 63;
  int tok = x[b * T + t];
  const float4* src = reinterpret_cast<const float4*>(emb + (size_t)tok * E);
  float4* dst = reinterpret_cast<float4*>(g_xs + (size_t)row * E);
  dst[threadIdx.x] = src[threadIdx.x];
}

// fp32 -> (hi, lo) bf16 split
__global__ void split_kernel(const float* __restrict__ in,
                             __nv_bfloat16* __restrict__ hi,
                             __nv_bfloat16* __restrict__ lo, int n) {
  int i = blockIdx.x * blockDim.x + threadIdx.x;
  if (i < n) {
    float x = in[i];
    __nv_bfloat16 h = __float2bfloat16(x);
    hi[i] = h;
    lo[i] = __float2bfloat16(x - __bfloat162float(h));
  }
}

// ---------------------------------------------------------------------------
// Split-bf16 tensor-core GEMM (warp-level HMMA, no sm_103a features):
// C[M,2048] = A[M,K] @ W[2048,K]^T + (b1+b2),
// computed as one TN GEMM over virtual K' = 3K:
//   segment 0: Ahi . Whi   segment 1: Alo . Whi   segment 2: Ahi . Wlo
// CTA tile 128x128, 8 warps (4m x 2n), warp tile 32x64, K-chunk 32,
// cp.async double-buffered smem (80B row stride -> conflict-free ldmatrix).
template <int K>
__global__ __launch_bounds__(256, 1)
void gemm_split_kernel(const __nv_bfloat16* __restrict__ Ahi,
                       const __nv_bfloat16* __restrict__ Alo,
                       const __nv_bfloat16* __restrict__ Whi,
                       const __nv_bfloat16* __restrict__ Wlo,
                       const float* __restrict__ b1,
                       const float* __restrict__ b2,
                       float* __restrict__ C) {
  constexpr int CPS = K / 32;        // chunks per segment
  constexpr int NCH = 3 * CPS;       // total chunks
  constexpr int LDS_EL = 40;         // smem row stride in bf16 (80 B)
  constexpr int TILE_EL = 128 * LDS_EL;   // one operand tile (5120 el, 10 KB)
  extern __shared__ __nv_bfloat16 smem[];   // [2 stages][A tile | W tile]
  __shared__ float bias_s[128];

  const int bn = blockIdx.x << 7;
  const int bm = blockIdx.y << 7;
  const int tid = threadIdx.x;
  const int lane = tid & 31;
  const int wid = tid >> 5;
  const int wm = (wid & 3) << 5;     // warp m offset (0..96)
  const int wn = (wid >> 2) << 6;    // warp n offset (0/64)

  if (tid < 128) bias_s[tid] = b1[bn + tid] + b2[bn + tid];

  const unsigned sb = s2u32(smem);
  const __nv_bfloat16* segA[3] = {Ahi, Alo, Ahi};
  const __nv_bfloat16* segW[3] = {Whi, Whi, Wlo};

  // loader: 1024 x 16B per stage (A: 512, W: 512), 4 per thread
  const int lrow = tid >> 2;         // 0..63
  const int lc = tid & 3;            // 16B column
  auto load_chunk = [&](int ch) {
    const int s = ch / CPS;
    const int k0 = (ch - s * CPS) << 5;
    const unsigned base = sb + (unsigned)(ch & 1) * (2 * TILE_EL * 2);
    const __nv_bfloat16* Ap = segA[s];
    const __nv_bfloat16* Wp = segW[s];
#pragma unroll
    for (int e = 0; e < 2; e++) {
      int r = lrow + (e << 6);
      unsigned so = (unsigned)(r * LDS_EL + lc * 8) * 2;
      cp_async16(base + so, Ap + (size_t)(bm + r) * K + k0 + lc * 8);
      cp_async16(base + TILE_EL * 2 + so,
                 Wp + (size_t)(bn + r) * K + k0 + lc * 8);
    }
    cp_commit();
  };

  load_chunk(0);
  load_chunk(1);

  float acc[2][8][4];
#pragma unroll
  for (int mi = 0; mi < 2; mi++)
#pragma unroll
    for (int ng = 0; ng < 8; ng++)
#pragma unroll
      for (int q = 0; q < 4; q++) acc[mi][ng][q] = 0.f;

  const int lrow16 = lane & 15;      // ldmatrix row
  const int lcol8 = (lane >> 4) << 3;  // ldmatrix 8-el col half

  for (int ch = 0; ch < NCH; ch++) {
    if (ch + 1 < NCH) cp_wait<1>(); else cp_wait<0>();
    __syncthreads();
    const unsigned base = sb + (unsigned)(ch & 1) * (2 * TILE_EL * 2);
    const unsigned baseW = base + TILE_EL * 2;
#pragma unroll
    for (int kk = 0; kk < 32; kk += 16) {
      unsigned a[2][4], bf[4][4];
#pragma unroll
      for (int mi = 0; mi < 2; mi++)
        ldmx4(a[mi], base + (unsigned)((wm + mi * 16 + lrow16) * LDS_EL +
                                       kk + lcol8) * 2);
#pragma unroll
      for (int ni = 0; ni < 4; ni++)
        ldmx4(bf[ni], baseW + (unsigned)((wn + ni * 16 + lrow16) * LDS_EL +
                                         kk + lcol8) * 2);
#pragma unroll
      for (int mi = 0; mi < 2; mi++)
#pragma unroll
        for (int ng = 0; ng < 8; ng++)
          hmma(acc[mi][ng], a[mi], bf[ng >> 1][ng & 1], bf[ng >> 1][2 + (ng & 1)]);
    }
    __syncthreads();   // all warps done reading before refill
    if (ch + 2 < NCH) load_chunk(ch + 2);
  }

  // Epilogue: acc + bias -> C.  d-frag: rows l/4 (+8), cols (l%4)*2 (+1)
  const int er = lane >> 2;
  const int ec = (lane & 3) << 1;
#pragma unroll
  for (int mi = 0; mi < 2; mi++) {
    int row0 = bm + wm + mi * 16 + er;
#pragma unroll
    for (int ng = 0; ng < 8; ng++) {
      int col = wn + ng * 8 + ec;
      float2 bv = make_float2(bias_s[col], bias_s[col + 1]);
      *reinterpret_cast<float2*>(&C[(size_t)row0 * G + bn + col]) =
          make_float2(acc[mi][ng][0] + bv.x, acc[mi][ng][1] + bv.y);
      *reinterpret_cast<float2*>(&C[(size_t)(row0 + 8) * G + bn + col]) =
          make_float2(acc[mi][ng][2] + bv.x, acc[mi][ng][3] + bv.y);
    }
  }
}

// ---------------------------------------------------------------------------
__device__ __forceinline__ float sigf(float x) {
  return 1.f / (1.f + __expf(-x));
}
__device__ __forceinline__ void fma2(unsigned long long& d,
                                     unsigned long long a,
                                     unsigned long long b) {
  asm("fma.rn.f32x2 %0, %1, %2, %0;" : "+l"(d) : "l"(a), "l"(b));
}
__device__ __forceinline__ unsigned long long dup2(float x) {
  unsigned long long r;
  asm("mov.b64 %0, {%1, %1};" : "=l"(r) : "f"(x));
  return r;
}
__device__ __forceinline__ float2 up2(unsigned long long v) {
  float2 r;
  asm("mov.b64 {%0, %1}, %2;" : "=f"(r.x), "=f"(r.y) : "l"(v));
  return r;
}

// Persistent BiLSTM recurrence (R5 known-good).
__global__ __launch_bounds__(256, 1)
void lstm_persistent(const float* __restrict__ pre_f,
                     const float* __restrict__ pre_b,
                     const float* __restrict__ Whh_f,
                     const float* __restrict__ Whh_b,
                     float* __restrict__ out) {
  extern __shared__ float smemf[];
  float* w_s = smemf;              // [512][32]  = 64 KB
  float* h_s = smemf + 512 * 32;   // [512][64]  = 128 KB (reused as red buffer)

  const int dir = blockIdx.x >> 6;
  const int jt = blockIdx.x & 63;
  const int jblk = jt << 3;
  const int tid = threadIdx.x;
  const int lane = tid & 31;
  const int warp = tid >> 5;
  const int kh = warp >> 2;
  const int wl = warp & 3;
  const int jp = lane >> 3;
  const int bpg = (wl << 3) + (lane & 7);
  const int b0 = bpg << 1;
  const int jg = jblk + (jp << 1);
  const float* Whh = dir ? Whh_b : Whh_f;
  const float* pre = dir ? pre_b : pre_f;

  for (int e = tid; e < 4096; e += 256) {
    int rl = e & 31;
    int k4 = (e >> 5) << 2;
    int g = rl >> 3, jl = rl & 7;
    float4 v = *reinterpret_cast<const float4*>(
        &Whh[((size_t)(g * 512 + jblk + jl)) * 512 + k4]);
    int col = ((jl >> 1) << 3) + (g << 1) + (jl & 1);
    w_s[(k4 + 0) * 32 + col] = v.x;
    w_s[(k4 + 1) * 32 + col] = v.y;
    w_s[(k4 + 2) * 32 + col] = v.z;
    w_s[(k4 + 3) * 32 + col] = v.w;
  }

  float c00 = 0.f, c01 = 0.f, c10 = 0.f, c11 = 0.f;
  const float* wbase = w_s + (jp << 3);
  const float* hb = h_s + b0;
  unsigned long long* red = reinterpret_cast<unsigned long long*>(h_s);
  const unsigned h_s_sa = s2u32(h_s);

  for (int t = 0; t < T; t++) {
    const int tt = dir ? (T - 1 - t) : t;
    const float* hp = g_hT[t & 1][dir];
    float* hn = g_hT[(t & 1) ^ 1][dir];

    __syncthreads();
    {
      const float4* src = reinterpret_cast<const float4*>(hp);
#pragma unroll
      for (int i = 0; i < 16; i++) {
        int idx = tid + (i << 8);
        cp_async16(h_s_sa + idx * 16, src + idx);
      }
      cp_commit();
#pragma unroll
      for (int i = 16; i < 32; i++) {
        int idx = tid + (i << 8);
        cp_async16(h_s_sa + idx * 16, src + idx);
      }
      cp_commit();
    }

    unsigned long long acc[2][4];
#pragma unroll
    for (int i = 0; i < 2; i++)
#pragma unroll
      for (int g = 0; g < 4; g++) acc[i][g] = 0ull;

    cp_wait<1>();
    __syncthreads();

#pragma unroll
    for (int chunk = 0; chunk < 2; chunk++) {
      const int kb = (chunk << 8) + (kh << 7);
#pragma unroll 8
      for (int k = kb; k < kb + 128; k++) {
        const ulonglong2* wk =
            reinterpret_cast<const ulonglong2*>(wbase + k * 32);
        ulonglong2 wA = wk[0];
        ulonglong2 wB = wk[1];
        float2 hv = *reinterpret_cast<const float2*>(hb + k * 64);
        unsigned long long h0 = dup2(hv.x);
        unsigned long long h1 = dup2(hv.y);
        fma2(acc[0][0], wA.x, h0); fma2(acc[1][0], wA.x, h1);
        fma2(acc[0][1], wA.y, h0); fma2(acc[1][1], wA.y, h1);
        fma2(acc[0][2], wB.x, h0); fma2(acc[1][2], wB.x, h1);
        fma2(acc[0][3], wB.y, h0); fma2(acc[1][3], wB.y, h1);
      }
      if (chunk == 0) {
        cp_wait<0>();
        __syncthreads();
      }
    }

    __syncthreads();
    if (kh == 1) {
      int base = tid - 128;
#pragma unroll
      for (int i = 0; i < 2; i++)
#pragma unroll
        for (int g = 0; g < 4; g++)
          red[(i * 4 + g) * 128 + base] = acc[i][g];
    }
    __syncthreads();

    if (kh == 0) {
      float hh[2][2];
#pragma unroll
      for (int i = 0; i < 2; i++) {
        int b = b0 + i;
        float2 a0 = up2(acc[i][0]), r0 = up2(red[(i * 4 + 0) * 128 + tid]);
        float2 a1 = up2(acc[i][1]), r1 = up2(red[(i * 4 + 1) * 128 + tid]);
        float2 a2 = up2(acc[i][2]), r2 = up2(red[(i * 4 + 2) * 128 + tid]);
        float2 a3 = up2(acc[i][3]), r3 = up2(red[(i * 4 + 3) * 128 + tid]);
        const float* pp = pre + ((size_t)tt * 64 + b) * 2048 + jg;
        float2 pi = *reinterpret_cast<const float2*>(pp);
        float2 pf = *reinterpret_cast<const float2*>(pp + 512);
        float2 pg = *reinterpret_cast<const float2*>(pp + 1024);
        float2 po = *reinterpret_cast<const float2*>(pp + 1536);
        float gi0 = a0.x + r0.x + pi.x, gi1 = a0.y + r0.y + pi.y;
        float gf0 = a1.x + r1.x + pf.x, gf1 = a1.y + r1.y + pf.y;
        float gg0 = a2.x + r2.x + pg.x, gg1 = a2.y + r2.y + pg.y;
        float go0 = a3.x + r3.x + po.x, go1 = a3.y + r3.y + po.y;
        float& cj0 = (i == 0) ? c00 : c10;
        float& cj1 = (i == 0) ? c01 : c11;
        cj0 = sigf(gf0) * cj0 + sigf(gi0) * tanhf(gg0);
        cj1 = sigf(gf1) * cj1 + sigf(gi1) * tanhf(gg1);
        float h0v = sigf(go0) * tanhf(cj0);
        float h1v = sigf(go1) * tanhf(cj1);
        hh[i][0] = h0v; hh[i][1] = h1v;
        *reinterpret_cast<float2*>(
            &out[((size_t)tt * 64 + b) * 1024 + dir * 512 + jg]) =
            make_float2(h0v, h1v);
      }
      *reinterpret_cast<float2*>(&hn[jg * 64 + b0]) =
          make_float2(hh[0][0], hh[1][0]);
      *reinterpret_cast<float2*>(&hn[(jg + 1) * 64 + b0]) =
          make_float2(hh[0][1], hh[1][1]);
    }

    if (t != T - 1) {
      __threadfence();
      __syncthreads();
      if (tid == 0) {
        unsigned target = (unsigned)(t + 1);
        if (atomicAdd(&g_barcnt[dir], 1u) == NBLK_PER_DIR - 1) {
          g_barcnt[dir] = 0;
          __threadfence();
          atomicExch((unsigned*)&g_bargen[dir], target);
        } else {
          while (g_bargen[dir] < target) __nanosleep(32);
        }
      }
      __syncthreads();
    }
  }
}

// ---------------------------------------------------------------------------
__global__ __launch_bounds__(256)
void fc_kernel(const float* __restrict__ inp,
               const float* __restrict__ Wt,
               const float* __restrict__ bias,
               float* __restrict__ out) {
  __shared__ float rs[8][1024];
  int r0 = blockIdx.x << 3;
#pragma unroll
  for (int l = threadIdx.x; l < 2048; l += 256) {
    int r = l >> 8, f4 = (l & 255) << 2;
    *reinterpret_cast<float4*>(&rs[r][f4]) =
        *reinterpret_cast<const float4*>(&inp[(size_t)(r0 + r) * 1024 + f4]);
  }
  __syncthreads();
  int r = threadIdx.x >> 5;
  int tg = threadIdx.x & 31;
  int tag2 = tg + 32;
  bool has2 = (tag2 < TAGS);
  float a0 = 0.f, a1 = 0.f;
  for (int k = 0; k < 1024; k += 4) {
    float4 xv = *reinterpret_cast<const float4*>(&rs[r][k]);
    float4 w0 = *reinterpret_cast<const float4*>(&Wt[(size_t)tg * 1024 + k]);
    a0 += xv.x * w0.x + xv.y * w0.y + xv.z * w0.z + xv.w * w0.w;
    if (has2) {
      float4 w1 = *reinterpret_cast<const float4*>(&Wt[(size_t)tag2 * 1024 + k]);
      a1 += xv.x * w1.x + xv.y * w1.y + xv.z * w1.z + xv.w * w1.w;
    }
  }
  int row = r0 + r;
  int tq = row >> 6, bb = row & 63;
  size_t obase = ((size_t)bb * T + tq) * TAGS;
  out[obase + tg] = a0 + bias[tg];
  if (has2) out[obase + tag2] = a1 + bias[tag2];
}

// ---------------------------------------------------------------------------
extern "C" void kernel_launch(void* const* d_in, const int* in_sizes, int n_in,
                              void* d_out, int out_size) {
  const int* x = (const int*)d_in[0];
  const float* emb = (const float*)d_in[2];
  const float* Wih_f1 = (const float*)d_in[3];
  const float* Whh_f1 = (const float*)d_in[4];
  const float* bih_f1 = (const float*)d_in[5];
  const float* bhh_f1 = (const float*)d_in[6];
  const float* Wih_b1 = (const float*)d_in[7];
  const float* Whh_b1 = (const float*)d_in[8];
  const float* bih_b1 = (const float*)d_in[9];
  const float* bhh_b1 = (const float*)d_in[10];
  const float* Wih_f2 = (const float*)d_in[11];
  const float* Whh_f2 = (const float*)d_in[12];
  const float* bih_f2 = (const float*)d_in[13];
  const float* bhh_f2 = (const float*)d_in[14];
  const float* Wih_b2 = (const float*)d_in[15];
  const float* Whh_b2 = (const float*)d_in[16];
  const float* bih_b2 = (const float*)d_in[17];
  const float* bhh_b2 = (const float*)d_in[18];
  const float* fcW = (const float*)d_in[19];
  const float* fcb = (const float*)d_in[20];
  float* out = (float*)d_out;

  float *xs, *pre_f, *pre_b, *out1, *out2;
  __nv_bfloat16 *ahi, *alo, *whi, *wlo;
  cudaGetSymbolAddress((void**)&xs, g_xs);
  cudaGetSymbolAddress((void**)&pre_f, g_pre_f);
  cudaGetSymbolAddress((void**)&pre_b, g_pre_b);
  cudaGetSymbolAddress((void**)&out1, g_out1);
  cudaGetSymbolAddress((void**)&out2, g_out2);
  cudaGetSymbolAddress((void**)&ahi, g_ahi);
  cudaGetSymbolAddress((void**)&alo, g_alo);
  cudaGetSymbolAddress((void**)&whi, g_whi);
  cudaGetSymbolAddress((void**)&wlo, g_wlo);

  constexpr int LSTM_SMEM = (512 * 32 + 512 * 64) * 4;   // 192 KB
  constexpr int GEMM_SMEM = 2 * 2 * 128 * 40 * 2;        // 40960 B
  static bool attr_set = false;
  if (!attr_set) {
    cudaFuncSetAttribute(lstm_persistent,
                         cudaFuncAttributeMaxDynamicSharedMemorySize, LSTM_SMEM);
    cudaFuncSetAttribute(gemm_split_kernel<512>,
                         cudaFuncAttributeMaxDynamicSharedMemorySize, GEMM_SMEM);
    cudaFuncSetAttribute(gemm_split_kernel<1024>,
                         cudaFuncAttributeMaxDynamicSharedMemorySize, GEMM_SMEM);
    attr_set = true;
  }

  dim3 gg(G / 128, M / 128);   // (16, 128)

  embed_kernel<<<M, 128>>>(x, emb);
  split_kernel<<<(M * E + 255) / 256, 256>>>(xs, ahi, alo, M * E);

  // Layer 1 (K = 512)
  init_layer_kernel<<<(4 * H * B + 255) / 256, 256>>>();
  split_kernel<<<(G * E + 255) / 256, 256>>>(Wih_f1, whi, wlo, G * E);
  gemm_split_kernel<512><<<gg, 256, GEMM_SMEM>>>(ahi, alo, whi, wlo,
                                                 bih_f1, bhh_f1, pre_f);
  split_kernel<<<(G * E + 255) / 256, 256>>>(Wih_b1, whi, wlo, G * E);
  gemm_split_kernel<512><<<gg, 256, GEMM_SMEM>>>(ahi, alo, whi, wlo,
                                                 bih_b1, bhh_b1, pre_b);
  lstm_persistent<<<2 * NBLK_PER_DIR, 256, LSTM_SMEM>>>(pre_f, pre_b,
                                                        Whh_f1, Whh_b1, out1);

  // Layer 2 (K = 1024)
  init_layer_kernel<<<(4 * H * B + 255) / 256, 256>>>();
  split_kernel<<<(M * 1024 + 255) / 256, 256>>>(out1, ahi, alo, M * 1024);
  split_kernel<<<(G * 1024 + 255) / 256, 256>>>(Wih_f2, whi, wlo, G * 1024);
  gemm_split_kernel<1024><<<gg, 256, GEMM_SMEM>>>(ahi, alo, whi, wlo,
                                                  bih_f2, bhh_f2, pre_f);
  split_kernel<<<(G * 1024 + 255) / 256, 256>>>(Wih_b2, whi, wlo, G * 1024);
  gemm_split_kernel<1024><<<gg, 256, GEMM_SMEM>>>(ahi, alo, whi, wlo,
                                                  bih_b2, bhh_b2, pre_b);
  lstm_persistent<<<2 * NBLK_PER_DIR, 256, LSTM_SMEM>>>(pre_f, pre_b,
                                                        Whh_f2, Whh_b2, out2);

  fc_kernel<<<M / 8, 256>>>(out2, fcW, fcb, out);
}

// round 9
// speedup vs baseline: 3.1863x; 1.2165x over previous
#include <cuda_runtime.h>
#include <cuda_bf16.h>
#include <math.h>

// Problem constants
namespace {
constexpr int B = 64, T = 256, E = 512, H = 512, TAGS = 50;
constexpr int G = 4 * H;   // 2048 (gate dim)
constexpr int M = T * B;   // 16384 rows
constexpr int NBLK_PER_DIR = 64;
constexpr int GH = G * H;  // 1M elements (one Whh)
}

// Single dynamic shared memory declaration for all kernels.
extern __shared__ char dynsmem[];

// Scratch (static device arrays — no cudaMalloc allowed)
__device__ float g_xs[M * E];
__device__ float g_pre_f[M * G];
__device__ float g_pre_b[M * G];
__device__ float g_out1[M * 2 * H];
__device__ float g_out2[M * 2 * H];
__device__ unsigned g_barcnt[2];
__device__ volatile unsigned g_bargen[2];
// bf16 split operands for tensor-core GEMMs
__device__ __align__(256) __nv_bfloat16 g_ahi[M * 1024];
__device__ __align__(256) __nv_bfloat16 g_alo[M * 1024];
__device__ __align__(256) __nv_bfloat16 g_whi[G * 1024];
__device__ __align__(256) __nv_bfloat16 g_wlo[G * 1024];
// recurrent weight splits (both dirs of current layer)
__device__ __align__(256) __nv_bfloat16 g_whhhi[2 * GH];
__device__ __align__(256) __nv_bfloat16 g_whhlo[2 * GH];
// h state in bf16 hi/lo, double buffered: [parity][dir][b*512 + j]
__device__ __align__(256) __nv_bfloat16 g_hbf_hi[2][2][B * H];
__device__ __align__(256) __nv_bfloat16 g_hbf_lo[2][2][B * H];

// ---------------------------------------------------------------------------
__device__ __forceinline__ unsigned s2u32(const void* p) {
  return static_cast<unsigned>(__cvta_generic_to_shared(p));
}
__device__ __forceinline__ void cp_async16(unsigned sa, const void* g) {
  asm volatile("cp.async.cg.shared.global [%0], [%1], 16;" :: "r"(sa), "l"(g));
}
__device__ __forceinline__ void cp_commit() {
  asm volatile("cp.async.commit_group;" ::: "memory");
}
template <int N>
__device__ __forceinline__ void cp_wait() {
  asm volatile("cp.async.wait_group %0;" :: "n"(N) : "memory");
}
__device__ __forceinline__ void ldmx4(unsigned* r, unsigned addr) {
  asm volatile("ldmatrix.sync.aligned.m8n8.x4.shared.b16 {%0,%1,%2,%3}, [%4];"
               : "=r"(r[0]), "=r"(r[1]), "=r"(r[2]), "=r"(r[3]) : "r"(addr));
}
__device__ __forceinline__ void hmma(float* d, const unsigned* a,
                                     unsigned b0, unsigned b1) {
  asm volatile(
      "mma.sync.aligned.m16n8k16.row.col.f32.bf16.bf16.f32 "
      "{%0,%1,%2,%3}, {%4,%5,%6,%7}, {%8,%9}, {%0,%1,%2,%3};"
      : "+f"(d[0]), "+f"(d[1]), "+f"(d[2]), "+f"(d[3])
      : "r"(a[0]), "r"(a[1]), "r"(a[2]), "r"(a[3]), "r"(b0), "r"(b1));
}
__device__ __forceinline__ float sigf(float x) {
  return 1.f / (1.f + __expf(-x));
}

// ---------------------------------------------------------------------------
__global__ void init_layer_kernel() {
  int i = blockIdx.x * blockDim.x + threadIdx.x;
  __nv_bfloat16* hh = &g_hbf_hi[0][0][0];
  __nv_bfloat16* hl = &g_hbf_lo[0][0][0];
  if (i < 2 * 2 * B * H) {
    hh[i] = __float2bfloat16(0.f);
    hl[i] = __float2bfloat16(0.f);
  }
  if (i < 2) { g_barcnt[i] = 0; g_bargen[i] = 0; }
}

__global__ void embed_kernel(const int* __restrict__ x,
                             const float* __restrict__ emb) {
  int row = blockIdx.x;
  int t = row >> 6;
  int b = row & 63;
  int tok = x[b * T + t];
  const float4* src = reinterpret_cast<const float4*>(emb + (size_t)tok * E);
  float4* dst = reinterpret_cast<float4*>(g_xs + (size_t)row * E);
  dst[threadIdx.x] = src[threadIdx.x];
}

// fp32 -> (hi, lo) bf16 split
__global__ void split_kernel(const float* __restrict__ in,
                             __nv_bfloat16* __restrict__ hi,
                             __nv_bfloat16* __restrict__ lo, int n) {
  int i = blockIdx.x * blockDim.x + threadIdx.x;
  if (i < n) {
    float x = in[i];
    __nv_bfloat16 h = __float2bfloat16(x);
    hi[i] = h;
    lo[i] = __float2bfloat16(x - __bfloat162float(h));
  }
}

// ---------------------------------------------------------------------------
// Split-bf16 HMMA GEMM (R7 known-good): C[M,2048]=A[M,K]@W[2048,K]^T + b1+b2
template <int K>
__global__ __launch_bounds__(256, 1)
void gemm_split_kernel(const __nv_bfloat16* __restrict__ Ahi,
                       const __nv_bfloat16* __restrict__ Alo,
                       const __nv_bfloat16* __restrict__ Whi,
                       const __nv_bfloat16* __restrict__ Wlo,
                       const float* __restrict__ b1,
                       const float* __restrict__ b2,
                       float* __restrict__ C) {
  constexpr int CPS = K / 32;
  constexpr int NCH = 3 * CPS;
  constexpr int LDS_EL = 40;
  constexpr int TILE_EL = 128 * LDS_EL;
  __nv_bfloat16* smem = reinterpret_cast<__nv_bfloat16*>(dynsmem);
  __shared__ float bias_s[128];

  const int bn = blockIdx.x << 7;
  const int bm = blockIdx.y << 7;
  const int tid = threadIdx.x;
  const int lane = tid & 31;
  const int wid = tid >> 5;
  const int wm = (wid & 3) << 5;
  const int wn = (wid >> 2) << 6;

  if (tid < 128) bias_s[tid] = b1[bn + tid] + b2[bn + tid];

  const unsigned sb = s2u32(smem);
  const __nv_bfloat16* segA[3] = {Ahi, Alo, Ahi};
  const __nv_bfloat16* segW[3] = {Whi, Whi, Wlo};

  const int lrow = tid >> 2;
  const int lc = tid & 3;
  auto load_chunk = [&](int ch) {
    const int s = ch / CPS;
    const int k0 = (ch - s * CPS) << 5;
    const unsigned base = sb + (unsigned)(ch & 1) * (2 * TILE_EL * 2);
    const __nv_bfloat16* Ap = segA[s];
    const __nv_bfloat16* Wp = segW[s];
#pragma unroll
    for (int e = 0; e < 2; e++) {
      int r = lrow + (e << 6);
      unsigned so = (unsigned)(r * LDS_EL + lc * 8) * 2;
      cp_async16(base + so, Ap + (size_t)(bm + r) * K + k0 + lc * 8);
      cp_async16(base + TILE_EL * 2 + so,
                 Wp + (size_t)(bn + r) * K + k0 + lc * 8);
    }
    cp_commit();
  };

  load_chunk(0);
  load_chunk(1);

  float acc[2][8][4];
#pragma unroll
  for (int mi = 0; mi < 2; mi++)
#pragma unroll
    for (int ng = 0; ng < 8; ng++)
#pragma unroll
      for (int q = 0; q < 4; q++) acc[mi][ng][q] = 0.f;

  const int lrow16 = lane & 15;
  const int lcol8 = (lane >> 4) << 3;

  for (int ch = 0; ch < NCH; ch++) {
    if (ch + 1 < NCH) cp_wait<1>(); else cp_wait<0>();
    __syncthreads();
    const unsigned base = sb + (unsigned)(ch & 1) * (2 * TILE_EL * 2);
    const unsigned baseW = base + TILE_EL * 2;
#pragma unroll
    for (int kk = 0; kk < 32; kk += 16) {
      unsigned a[2][4], bf[4][4];
#pragma unroll
      for (int mi = 0; mi < 2; mi++)
        ldmx4(a[mi], base + (unsigned)((wm + mi * 16 + lrow16) * LDS_EL +
                                       kk + lcol8) * 2);
#pragma unroll
      for (int ni = 0; ni < 4; ni++)
        ldmx4(bf[ni], baseW + (unsigned)((wn + ni * 16 + lrow16) * LDS_EL +
                                         kk + lcol8) * 2);
#pragma unroll
      for (int mi = 0; mi < 2; mi++)
#pragma unroll
        for (int ng = 0; ng < 8; ng++)
          hmma(acc[mi][ng], a[mi], bf[ng >> 1][ng & 1], bf[ng >> 1][2 + (ng & 1)]);
    }
    __syncthreads();
    if (ch + 2 < NCH) load_chunk(ch + 2);
  }

  const int er = lane >> 2;
  const int ec = (lane & 3) << 1;
#pragma unroll
  for (int mi = 0; mi < 2; mi++) {
    int row0 = bm + wm + mi * 16 + er;
#pragma unroll
    for (int ng = 0; ng < 8; ng++) {
      int col = wn + ng * 8 + ec;
      float2 bv = make_float2(bias_s[col], bias_s[col + 1]);
      *reinterpret_cast<float2*>(&C[(size_t)row0 * G + bn + col]) =
          make_float2(acc[mi][ng][0] + bv.x, acc[mi][ng][1] + bv.y);
      *reinterpret_cast<float2*>(&C[(size_t)(row0 + 8) * G + bn + col]) =
          make_float2(acc[mi][ng][2] + bv.x, acc[mi][ng][3] + bv.y);
    }
  }
}

// ---------------------------------------------------------------------------
// Persistent BiLSTM recurrence with split-bf16 HMMA step GEMM.
// 128 blocks: dir = bx>>6, j-tile = bx&63 (8 hidden units = 32 gate-cols,
// B-rows ordered g*8+jl). 256 threads = 4 m-warps x 2 split-K halves.
// Whh slice (32 x 512, hi+lo) resident in smem; h (64x512 hi+lo bf16)
// cp.async double-buffered in 128-k chunks. 12 HMMA per k16 per warp
// (Ah.Wh + Ah.Wl + Al.Wh). d-frag gives each low-thread 2b x 2j x 4 gates ->
// in-register c/h update, h written back as bf16 hi/lo + fp32 out.
__global__ __launch_bounds__(256, 1)
void lstm_persistent(const float* __restrict__ pre_f,
                     const float* __restrict__ pre_b,
                     const __nv_bfloat16* __restrict__ whh_hi,
                     const __nv_bfloat16* __restrict__ whh_lo,
                     float* __restrict__ out) {
  // smem layout (bytes):
  //   w_hi  [32 rows x 520 el]   @ 0        (33280)
  //   w_lo                       @ 33280    (33280)
  //   A buf0 hi|lo [64 x 136 el] @ 66560    (17408 + 17408)
  //   A buf1 hi|lo               @ 101376   (34816)
  //   red   [4mw x 4g x 32 lanes x float4]  @ 136192 (8192)
  constexpr int WSTR = 520;    // W smem stride (elements)
  constexpr int ASTR = 136;    // A smem stride (elements)
  constexpr unsigned W_LO = 33280;
  constexpr unsigned A_BASE = 66560;
  constexpr unsigned A_BUFSZ = 34816;
  constexpr unsigned A_LOSZ = 17408;
  constexpr unsigned RED_OFF = 136192;
  char* smem = dynsmem;
  const unsigned sb = s2u32(smem);
  float4* red = reinterpret_cast<float4*>(smem + RED_OFF);

  const int dir = blockIdx.x >> 6;
  const int jt = blockIdx.x & 63;
  const int jblk = jt << 3;
  const int tid = threadIdx.x;
  const int lane = tid & 31;
  const int warp = tid >> 5;
  const int kh = warp >> 2;            // split-K half
  const int mw = warp & 3;             // m-warp (batches mw*16..+15)
  const int wm = mw << 4;
  const int lrow16 = lane & 15;
  const int lcol8 = (lane >> 4) << 3;
  const float* pre = dir ? pre_b : pre_f;
  const __nv_bfloat16* whi = whh_hi + (size_t)dir * GH;
  const __nv_bfloat16* wlo = whh_lo + (size_t)dir * GH;

  // Stage Whh slice (rows r = g*8+jl -> Whh row g*512 + jblk + jl), hi & lo.
  for (int e = tid; e < 2048; e += 256) {
    int r = e >> 6;                 // 0..31
    int c16 = e & 63;               // 16B col (512 el = 64 chunks)
    int g = r >> 3, jl = r & 7;
    size_t go = (size_t)(g * 512 + jblk + jl) * 512 + c16 * 8;
    unsigned so = (unsigned)(r * WSTR + c16 * 8) * 2;
    *reinterpret_cast<uint4*>(smem + so) =
        *reinterpret_cast<const uint4*>(whi + go);
    *reinterpret_cast<uint4*>(smem + W_LO + so) =
        *reinterpret_cast<const uint4*>(wlo + go);
  }

  float c_st[2][2];                 // [bhalf(+8)][jhalf] (low warps only)
  c_st[0][0] = c_st[0][1] = c_st[1][0] = c_st[1][1] = 0.f;

  const int er = lane >> 2;
  const int ec = (lane & 3) << 1;
  const int jg = jblk + ec;

  // A-chunk loader: 64 rows x 128 k (hi+lo), 8 cp.async16/thread
  auto load_chunk = [&](const __nv_bfloat16* hhi, const __nv_bfloat16* hlo,
                        int ch) {
    const int k0 = ch << 7;
    const unsigned base = sb + A_BASE + (unsigned)(ch & 1) * A_BUFSZ;
    const int r0 = tid >> 2;        // 0..63
    const int c0 = tid & 3;         // 4 16B cols of 8 (128 el = 16 chunks)
#pragma unroll
    for (int e = 0; e < 4; e++) {
      int c16 = c0 + (e << 2);
      unsigned so = (unsigned)(r0 * ASTR + c16 * 8) * 2;
      size_t go = (size_t)r0 * 512 + k0 + c16 * 8;
      cp_async16(base + so, hhi + go);
      cp_async16(base + A_LOSZ + so, hlo + go);
    }
    cp_commit();
  };

  for (int t = 0; t < T; t++) {
    const int tt = dir ? (T - 1 - t) : t;
    const int par = t & 1;
    const __nv_bfloat16* hhi = g_hbf_hi[par][dir];
    const __nv_bfloat16* hlo = g_hbf_lo[par][dir];
    __nv_bfloat16* nhi = g_hbf_hi[par ^ 1][dir];
    __nv_bfloat16* nlo = g_hbf_lo[par ^ 1][dir];

    __syncthreads();   // prev step fully done (incl. red reads)
    load_chunk(hhi, hlo, 0);
    load_chunk(hhi, hlo, 1);

    float acc[4][4];   // [gate][frag]
#pragma unroll
    for (int g = 0; g < 4; g++)
#pragma unroll
      for (int q = 0; q < 4; q++) acc[g][q] = 0.f;

    for (int ch = 0; ch < 4; ch++) {
      if (ch < 3) cp_wait<1>(); else cp_wait<0>();
      __syncthreads();
      const unsigned abase = sb + A_BASE + (unsigned)(ch & 1) * A_BUFSZ;
      const int kloc = kh << 6;          // 0 or 64 within chunk
      const int kglob = (ch << 7) + kloc;
#pragma unroll
      for (int kk = 0; kk < 64; kk += 16) {
        unsigned ah[4], al[4], bh[2][4], bl[2][4];
        unsigned aoff = (unsigned)(lrow16 * ASTR + kloc + kk + lcol8) * 2;
        ldmx4(ah, abase + (unsigned)(wm * ASTR) * 2 + aoff);
        ldmx4(al, abase + A_LOSZ + (unsigned)(wm * ASTR) * 2 + aoff);
#pragma unroll
        for (int ni = 0; ni < 2; ni++) {
          unsigned woff =
              (unsigned)((ni * 16 + lrow16) * WSTR + kglob + kk + lcol8) * 2;
          ldmx4(bh[ni], sb + woff);
          ldmx4(bl[ni], sb + W_LO + woff);
        }
#pragma unroll
        for (int g = 0; g < 4; g++) {
          unsigned h0 = bh[g >> 1][g & 1], h1 = bh[g >> 1][2 + (g & 1)];
          unsigned l0 = bl[g >> 1][g & 1], l1 = bl[g >> 1][2 + (g & 1)];
          hmma(acc[g], ah, h0, h1);
          hmma(acc[g], ah, l0, l1);
          hmma(acc[g], al, h0, h1);
        }
      }
      __syncthreads();
      if (ch + 2 < 4) load_chunk(hhi, hlo, ch + 2);
    }

    // split-K reduce: upper half dumps, lower half combines + epilogue
    if (kh == 1) {
#pragma unroll
      for (int g = 0; g < 4; g++)
        red[(mw * 4 + g) * 32 + lane] =
            make_float4(acc[g][0], acc[g][1], acc[g][2], acc[g][3]);
    }
    __syncthreads();

    if (kh == 0) {
#pragma unroll
      for (int g = 0; g < 4; g++) {
        float4 r = red[(mw * 4 + g) * 32 + lane];
        acc[g][0] += r.x; acc[g][1] += r.y; acc[g][2] += r.z; acc[g][3] += r.w;
      }
      // gates for batches b0 = wm+er, b1 = b0+8; hidden j = jg, jg+1
#pragma unroll
      for (int i = 0; i < 2; i++) {
        int b = wm + er + i * 8;
        const float* pp = pre + ((size_t)tt * 64 + b) * 2048 + jg;
        float2 pi = *reinterpret_cast<const float2*>(pp);
        float2 pf = *reinterpret_cast<const float2*>(pp + 512);
        float2 pg = *reinterpret_cast<const float2*>(pp + 1024);
        float2 po = *reinterpret_cast<const float2*>(pp + 1536);
        float gi0 = acc[0][i * 2] + pi.x, gi1 = acc[0][i * 2 + 1] + pi.y;
        float gf0 = acc[1][i * 2] + pf.x, gf1 = acc[1][i * 2 + 1] + pf.y;
        float gg0 = acc[2][i * 2] + pg.x, gg1 = acc[2][i * 2 + 1] + pg.y;
        float go0 = acc[3][i * 2] + po.x, go1 = acc[3][i * 2 + 1] + po.y;
        float c0 = sigf(gf0) * c_st[i][0] + sigf(gi0) * tanhf(gg0);
        float c1 = sigf(gf1) * c_st[i][1] + sigf(gi1) * tanhf(gg1);
        c_st[i][0] = c0; c_st[i][1] = c1;
        float h0 = sigf(go0) * tanhf(c0);
        float h1 = sigf(go1) * tanhf(c1);
        *reinterpret_cast<float2*>(
            &out[((size_t)tt * 64 + b) * 1024 + dir * 512 + jg]) =
            make_float2(h0, h1);
        // bf16 hi/lo write-back for next step's A operand
        __nv_bfloat16 h0h = __float2bfloat16(h0);
        __nv_bfloat16 h1h = __float2bfloat16(h1);
        __nv_bfloat16 h0l = __float2bfloat16(h0 - __bfloat162float(h0h));
        __nv_bfloat16 h1l = __float2bfloat16(h1 - __bfloat162float(h1h));
        __nv_bfloat162 vh; vh.x = h0h; vh.y = h1h;
        __nv_bfloat162 vl; vl.x = h0l; vl.y = h1l;
        *reinterpret_cast<__nv_bfloat162*>(&nhi[b * 512 + jg]) = vh;
        *reinterpret_cast<__nv_bfloat162*>(&nlo[b * 512 + jg]) = vl;
      }
    }

    // per-direction grid barrier before next step reads nhi/nlo
    if (t != T - 1) {
      __threadfence();
      __syncthreads();
      if (tid == 0) {
        unsigned target = (unsigned)(t + 1);
        if (atomicAdd(&g_barcnt[dir], 1u) == NBLK_PER_DIR - 1) {
          g_barcnt[dir] = 0;
          __threadfence();
          atomicExch((unsigned*)&g_bargen[dir], target);
        } else {
          while (g_bargen[dir] < target) __nanosleep(32);
        }
      }
      __syncthreads();
    }
  }
}

// ---------------------------------------------------------------------------
__global__ __launch_bounds__(256)
void fc_kernel(const float* __restrict__ inp,
               const float* __restrict__ Wt,
               const float* __restrict__ bias,
               float* __restrict__ out) {
  __shared__ float rs[8][1024];
  int r0 = blockIdx.x << 3;
#pragma unroll
  for (int l = threadIdx.x; l < 2048; l += 256) {
    int r = l >> 8, f4 = (l & 255) << 2;
    *reinterpret_cast<float4*>(&rs[r][f4]) =
        *reinterpret_cast<const float4*>(&inp[(size_t)(r0 + r) * 1024 + f4]);
  }
  __syncthreads();
  int r = threadIdx.x >> 5;
  int tg = threadIdx.x & 31;
  int tag2 = tg + 32;
  bool has2 = (tag2 < TAGS);
  float a0 = 0.f, a1 = 0.f;
  for (int k = 0; k < 1024; k += 4) {
    float4 xv = *reinterpret_cast<const float4*>(&rs[r][k]);
    float4 w0 = *reinterpret_cast<const float4*>(&Wt[(size_t)tg * 1024 + k]);
    a0 += xv.x * w0.x + xv.y * w0.y + xv.z * w0.z + xv.w * w0.w;
    if (has2) {
      float4 w1 = *reinterpret_cast<const float4*>(&Wt[(size_t)tag2 * 1024 + k]);
      a1 += xv.x * w1.x + xv.y * w1.y + xv.z * w1.z + xv.w * w1.w;
    }
  }
  int row = r0 + r;
  int tq = row >> 6, bb = row & 63;
  size_t obase = ((size_t)bb * T + tq) * TAGS;
  out[obase + tg] = a0 + bias[tg];
  if (has2) out[obase + tag2] = a1 + bias[tag2];
}

// ---------------------------------------------------------------------------
extern "C" void kernel_launch(void* const* d_in, const int* in_sizes, int n_in,
                              void* d_out, int out_size) {
  const int* x = (const int*)d_in[0];
  const float* emb = (const float*)d_in[2];
  const float* Wih_f1 = (const float*)d_in[3];
  const float* Whh_f1 = (const float*)d_in[4];
  const float* bih_f1 = (const float*)d_in[5];
  const float* bhh_f1 = (const float*)d_in[6];
  const float* Wih_b1 = (const float*)d_in[7];
  const float* Whh_b1 = (const float*)d_in[8];
  const float* bih_b1 = (const float*)d_in[9];
  const float* bhh_b1 = (const float*)d_in[10];
  const float* Wih_f2 = (const float*)d_in[11];
  const float* Whh_f2 = (const float*)d_in[12];
  const float* bih_f2 = (const float*)d_in[13];
  const float* bhh_f2 = (const float*)d_in[14];
  const float* Wih_b2 = (const float*)d_in[15];
  const float* Whh_b2 = (const float*)d_in[16];
  const float* bih_b2 = (const float*)d_in[17];
  const float* bhh_b2 = (const float*)d_in[18];
  const float* fcW = (const float*)d_in[19];
  const float* fcb = (const float*)d_in[20];
  float* out = (float*)d_out;

  float *xs, *pre_f, *pre_b, *out1, *out2;
  __nv_bfloat16 *ahi, *alo, *whi, *wlo, *whhhi, *whhlo;
  cudaGetSymbolAddress((void**)&xs, g_xs);
  cudaGetSymbolAddress((void**)&pre_f, g_pre_f);
  cudaGetSymbolAddress((void**)&pre_b, g_pre_b);
  cudaGetSymbolAddress((void**)&out1, g_out1);
  cudaGetSymbolAddress((void**)&out2, g_out2);
  cudaGetSymbolAddress((void**)&ahi, g_ahi);
  cudaGetSymbolAddress((void**)&alo, g_alo);
  cudaGetSymbolAddress((void**)&whi, g_whi);
  cudaGetSymbolAddress((void**)&wlo, g_wlo);
  cudaGetSymbolAddress((void**)&whhhi, g_whhhi);
  cudaGetSymbolAddress((void**)&whhlo, g_whhlo);

  constexpr int LSTM_SMEM = 136192 + 8192;        // 144,384 B
  constexpr int GEMM_SMEM = 2 * 2 * 128 * 40 * 2; // 40,960 B
  static bool attr_set = false;
  if (!attr_set) {
    cudaFuncSetAttribute(lstm_persistent,
                         cudaFuncAttributeMaxDynamicSharedMemorySize, LSTM_SMEM);
    cudaFuncSetAttribute(gemm_split_kernel<512>,
                         cudaFuncAttributeMaxDynamicSharedMemorySize, GEMM_SMEM);
    cudaFuncSetAttribute(gemm_split_kernel<1024>,
                         cudaFuncAttributeMaxDynamicSharedMemorySize, GEMM_SMEM);
    attr_set = true;
  }

  dim3 gg(G / 128, M / 128);   // (16, 128)

  embed_kernel<<<M, 128>>>(x, emb);
  split_kernel<<<(M * E + 255) / 256, 256>>>(xs, ahi, alo, M * E);

  // Layer 1 (K = 512)
  init_layer_kernel<<<(2 * 2 * B * H + 255) / 256, 256>>>();
  split_kernel<<<(G * E + 255) / 256, 256>>>(Wih_f1, whi, wlo, G * E);
  gemm_split_kernel<512><<<gg, 256, GEMM_SMEM>>>(ahi, alo, whi, wlo,
                                                 bih_f1, bhh_f1, pre_f);
  split_kernel<<<(G * E + 255) / 256, 256>>>(Wih_b1, whi, wlo, G * E);
  gemm_split_kernel<512><<<gg, 256, GEMM_SMEM>>>(ahi, alo, whi, wlo,
                                                 bih_b1, bhh_b1, pre_b);
  split_kernel<<<(GH + 255) / 256, 256>>>(Whh_f1, whhhi, whhlo, GH);
  split_kernel<<<(GH + 255) / 256, 256>>>(Whh_b1, whhhi + GH, whhlo + GH, GH);
  lstm_persistent<<<2 * NBLK_PER_DIR, 256, LSTM_SMEM>>>(pre_f, pre_b,
                                                        whhhi, whhlo, out1);

  // Layer 2 (K = 1024)
  init_layer_kernel<<<(2 * 2 * B * H + 255) / 256, 256>>>();
  split_kernel<<<(M * 1024 + 255) / 256, 256>>>(out1, ahi, alo, M * 1024);
  split_kernel<<<(G * 1024 + 255) / 256, 256>>>(Wih_f2, whi, wlo, G * 1024);
  gemm_split_kernel<1024><<<gg, 256, GEMM_SMEM>>>(ahi, alo, whi, wlo,
                                                  bih_f2, bhh_f2, pre_f);
  split_kernel<<<(G * 1024 + 255) / 256, 256>>>(Wih_b2, whi, wlo, G * 1024);
  gemm_split_kernel<1024><<<gg, 256, GEMM_SMEM>>>(ahi, alo, whi, wlo,
                                                  bih_b2, bhh_b2, pre_b);
  split_kernel<<<(GH + 255) / 256, 256>>>(Whh_f2, whhhi, whhlo, GH);
  split_kernel<<<(GH + 255) / 256, 256>>>(Whh_b2, whhhi + GH, whhlo + GH, GH);
  lstm_persistent<<<2 * NBLK_PER_DIR, 256, LSTM_SMEM>>>(pre_f, pre_b,
                                                        whhhi, whhlo, out2);

  fc_kernel<<<M / 8, 256>>>(out2, fcW, fcb, out);
}

// round 10
// speedup vs baseline: 3.6240x; 1.1374x over previous
#include <cuda_runtime.h>
#include <cuda_bf16.h>
#include <math.h>

// Problem constants
namespace {
constexpr int B = 64, T = 256, E = 512, H = 512, TAGS = 50;
constexpr int G = 4 * H;   // 2048 (gate dim)
constexpr int M = T * B;   // 16384 rows
constexpr int NBLK_PER_DIR = 64;
constexpr int GH = G * H;  // 1M elements (one Whh)
}

// Single dynamic shared memory declaration for all kernels.
extern __shared__ char dynsmem[];

// Scratch (static device arrays — no cudaMalloc allowed)
__device__ float g_xs[M * E];
__device__ float g_pre_f[M * G];
__device__ float g_pre_b[M * G];
__device__ float g_out1[M * 2 * H];
__device__ float g_out2[M * 2 * H];
__device__ unsigned g_barcnt[2];
__device__ volatile unsigned g_bargen[2];
// bf16 split operands for tensor-core GEMMs
__device__ __align__(256) __nv_bfloat16 g_ahi[M * 1024];
__device__ __align__(256) __nv_bfloat16 g_alo[M * 1024];
__device__ __align__(256) __nv_bfloat16 g_whi[G * 1024];
__device__ __align__(256) __nv_bfloat16 g_wlo[G * 1024];
// recurrent weight splits (both dirs of current layer)
__device__ __align__(256) __nv_bfloat16 g_whhhi[2 * GH];
__device__ __align__(256) __nv_bfloat16 g_whhlo[2 * GH];
// h state in bf16 hi/lo, double buffered: [parity][dir][b*512 + j]
__device__ __align__(256) __nv_bfloat16 g_hbf_hi[2][2][B * H];
__device__ __align__(256) __nv_bfloat16 g_hbf_lo[2][2][B * H];

// ---------------------------------------------------------------------------
__device__ __forceinline__ unsigned s2u32(const void* p) {
  return static_cast<unsigned>(__cvta_generic_to_shared(p));
}
__device__ __forceinline__ void cp_async16(unsigned sa, const void* g) {
  asm volatile("cp.async.cg.shared.global [%0], [%1], 16;" :: "r"(sa), "l"(g));
}
__device__ __forceinline__ void cp_commit() {
  asm volatile("cp.async.commit_group;" ::: "memory");
}
template <int N>
__device__ __forceinline__ void cp_wait() {
  asm volatile("cp.async.wait_group %0;" :: "n"(N) : "memory");
}
__device__ __forceinline__ void ldmx4(unsigned* r, unsigned addr) {
  asm volatile("ldmatrix.sync.aligned.m8n8.x4.shared.b16 {%0,%1,%2,%3}, [%4];"
               : "=r"(r[0]), "=r"(r[1]), "=r"(r[2]), "=r"(r[3]) : "r"(addr));
}
__device__ __forceinline__ void hmma(float* d, const unsigned* a,
                                     unsigned b0, unsigned b1) {
  asm volatile(
      "mma.sync.aligned.m16n8k16.row.col.f32.bf16.bf16.f32 "
      "{%0,%1,%2,%3}, {%4,%5,%6,%7}, {%8,%9}, {%0,%1,%2,%3};"
      : "+f"(d[0]), "+f"(d[1]), "+f"(d[2]), "+f"(d[3])
      : "r"(a[0]), "r"(a[1]), "r"(a[2]), "r"(a[3]), "r"(b0), "r"(b1));
}
__device__ __forceinline__ float sigf(float x) {
  return __fdividef(1.f, 1.f + __expf(-x));
}
// tanh(x) = 1 - 2/(e^{2x}+1); overflow-safe (e->inf => 1, e->0 => -1)
__device__ __forceinline__ float tanhf_fast(float x) {
  float e = __expf(2.f * x);
  return 1.f - __fdividef(2.f, e + 1.f);
}

// ---------------------------------------------------------------------------
__global__ void init_layer_kernel() {
  int i = blockIdx.x * blockDim.x + threadIdx.x;
  __nv_bfloat16* hh = &g_hbf_hi[0][0][0];
  __nv_bfloat16* hl = &g_hbf_lo[0][0][0];
  if (i < 2 * 2 * B * H) {
    hh[i] = __float2bfloat16(0.f);
    hl[i] = __float2bfloat16(0.f);
  }
  if (i < 2) { g_barcnt[i] = 0; g_bargen[i] = 0; }
}

__global__ void embed_kernel(const int* __restrict__ x,
                             const float* __restrict__ emb) {
  int row = blockIdx.x;
  int t = row >> 6;
  int b = row & 63;
  int tok = x[b * T + t];
  const float4* src = reinterpret_cast<const float4*>(emb + (size_t)tok * E);
  float4* dst = reinterpret_cast<float4*>(g_xs + (size_t)row * E);
  dst[threadIdx.x] = src[threadIdx.x];
}

// fp32 -> (hi, lo) bf16 split
__global__ void split_kernel(const float* __restrict__ in,
                             __nv_bfloat16* __restrict__ hi,
                             __nv_bfloat16* __restrict__ lo, int n) {
  int i = blockIdx.x * blockDim.x + threadIdx.x;
  if (i < n) {
    float x = in[i];
    __nv_bfloat16 h = __float2bfloat16(x);
    hi[i] = h;
    lo[i] = __float2bfloat16(x - __bfloat162float(h));
  }
}

// ---------------------------------------------------------------------------
// Split-bf16 HMMA GEMM (R7 known-good): C[M,2048]=A[M,K]@W[2048,K]^T + b1+b2
template <int K>
__global__ __launch_bounds__(256, 1)
void gemm_split_kernel(const __nv_bfloat16* __restrict__ Ahi,
                       const __nv_bfloat16* __restrict__ Alo,
                       const __nv_bfloat16* __restrict__ Whi,
                       const __nv_bfloat16* __restrict__ Wlo,
                       const float* __restrict__ b1,
                       const float* __restrict__ b2,
                       float* __restrict__ C) {
  constexpr int CPS = K / 32;
  constexpr int NCH = 3 * CPS;
  constexpr int LDS_EL = 40;
  constexpr int TILE_EL = 128 * LDS_EL;
  __nv_bfloat16* smem = reinterpret_cast<__nv_bfloat16*>(dynsmem);
  __shared__ float bias_s[128];

  const int bn = blockIdx.x << 7;
  const int bm = blockIdx.y << 7;
  const int tid = threadIdx.x;
  const int lane = tid & 31;
  const int wid = tid >> 5;
  const int wm = (wid & 3) << 5;
  const int wn = (wid >> 2) << 6;

  if (tid < 128) bias_s[tid] = b1[bn + tid] + b2[bn + tid];

  const unsigned sb = s2u32(smem);
  const __nv_bfloat16* segA[3] = {Ahi, Alo, Ahi};
  const __nv_bfloat16* segW[3] = {Whi, Whi, Wlo};

  const int lrow = tid >> 2;
  const int lc = tid & 3;
  auto load_chunk = [&](int ch) {
    const int s = ch / CPS;
    const int k0 = (ch - s * CPS) << 5;
    const unsigned base = sb + (unsigned)(ch & 1) * (2 * TILE_EL * 2);
    const __nv_bfloat16* Ap = segA[s];
    const __nv_bfloat16* Wp = segW[s];
#pragma unroll
    for (int e = 0; e < 2; e++) {
      int r = lrow + (e << 6);
      unsigned so = (unsigned)(r * LDS_EL + lc * 8) * 2;
      cp_async16(base + so, Ap + (size_t)(bm + r) * K + k0 + lc * 8);
      cp_async16(base + TILE_EL * 2 + so,
                 Wp + (size_t)(bn + r) * K + k0 + lc * 8);
    }
    cp_commit();
  };

  load_chunk(0);
  load_chunk(1);

  float acc[2][8][4];
#pragma unroll
  for (int mi = 0; mi < 2; mi++)
#pragma unroll
    for (int ng = 0; ng < 8; ng++)
#pragma unroll
      for (int q = 0; q < 4; q++) acc[mi][ng][q] = 0.f;

  const int lrow16 = lane & 15;
  const int lcol8 = (lane >> 4) << 3;

  for (int ch = 0; ch < NCH; ch++) {
    if (ch + 1 < NCH) cp_wait<1>(); else cp_wait<0>();
    __syncthreads();
    const unsigned base = sb + (unsigned)(ch & 1) * (2 * TILE_EL * 2);
    const unsigned baseW = base + TILE_EL * 2;
#pragma unroll
    for (int kk = 0; kk < 32; kk += 16) {
      unsigned a[2][4], bf[4][4];
#pragma unroll
      for (int mi = 0; mi < 2; mi++)
        ldmx4(a[mi], base + (unsigned)((wm + mi * 16 + lrow16) * LDS_EL +
                                       kk + lcol8) * 2);
#pragma unroll
      for (int ni = 0; ni < 4; ni++)
        ldmx4(bf[ni], baseW + (unsigned)((wn + ni * 16 + lrow16) * LDS_EL +
                                         kk + lcol8) * 2);
#pragma unroll
      for (int mi = 0; mi < 2; mi++)
#pragma unroll
        for (int ng = 0; ng < 8; ng++)
          hmma(acc[mi][ng], a[mi], bf[ng >> 1][ng & 1], bf[ng >> 1][2 + (ng & 1)]);
    }
    __syncthreads();
    if (ch + 2 < NCH) load_chunk(ch + 2);
  }

  const int er = lane >> 2;
  const int ec = (lane & 3) << 1;
#pragma unroll
  for (int mi = 0; mi < 2; mi++) {
    int row0 = bm + wm + mi * 16 + er;
#pragma unroll
    for (int ng = 0; ng < 8; ng++) {
      int col = wn + ng * 8 + ec;
      float2 bv = make_float2(bias_s[col], bias_s[col + 1]);
      *reinterpret_cast<float2*>(&C[(size_t)row0 * G + bn + col]) =
          make_float2(acc[mi][ng][0] + bv.x, acc[mi][ng][1] + bv.y);
      *reinterpret_cast<float2*>(&C[(size_t)(row0 + 8) * G + bn + col]) =
          make_float2(acc[mi][ng][2] + bv.x, acc[mi][ng][3] + bv.y);
    }
  }
}

// ---------------------------------------------------------------------------
// Persistent BiLSTM recurrence with split-bf16 HMMA step GEMM.
// R10: 2 k-chunks of 256 (fewer syncs), pre-gate slice prefetched to smem
// via cp.async (overlapped with MMA), fast tanh/sigmoid in epilogue.
__global__ __launch_bounds__(256, 1)
void lstm_persistent(const float* __restrict__ pre_f,
                     const float* __restrict__ pre_b,
                     const __nv_bfloat16* __restrict__ whh_hi,
                     const __nv_bfloat16* __restrict__ whh_lo,
                     float* __restrict__ out) {
  // smem layout (bytes):
  //   w_hi  [32 x 520 el]        @ 0        (33280)
  //   w_lo                       @ 33280    (33280)
  //   A buf0 hi|lo [64 x 264 el] @ 66560    (33792 + 33792)
  //   A buf1 hi|lo               @ 134144   (67584)
  //   pre_s [64 b x 32 f]        @ 201728   (8192)
  //   red   [4mw x 4g x 32 x f4] @ 209920   (8192)
  constexpr int WSTR = 520;
  constexpr int ASTR = 264;
  constexpr unsigned W_LO = 33280;
  constexpr unsigned A_BASE = 66560;
  constexpr unsigned A_LOSZ = 33792;
  constexpr unsigned A_BUFSZ = 67584;
  constexpr unsigned PRE_OFF = 201728;
  constexpr unsigned RED_OFF = 209920;
  char* smem = dynsmem;
  const unsigned sb = s2u32(smem);
  float* pre_s = reinterpret_cast<float*>(smem + PRE_OFF);
  float4* red = reinterpret_cast<float4*>(smem + RED_OFF);

  const int dir = blockIdx.x >> 6;
  const int jt = blockIdx.x & 63;
  const int jblk = jt << 3;
  const int tid = threadIdx.x;
  const int lane = tid & 31;
  const int warp = tid >> 5;
  const int kh = warp >> 2;            // split-K half
  const int mw = warp & 3;             // m-warp (batches mw*16..+15)
  const int wm = mw << 4;
  const int lrow16 = lane & 15;
  const int lcol8 = (lane >> 4) << 3;
  const float* pre = dir ? pre_b : pre_f;
  const __nv_bfloat16* whi = whh_hi + (size_t)dir * GH;
  const __nv_bfloat16* wlo = whh_lo + (size_t)dir * GH;

  // Stage Whh slice (rows r = g*8+jl -> Whh row g*512 + jblk + jl), hi & lo.
  for (int e = tid; e < 2048; e += 256) {
    int r = e >> 6;
    int c16 = e & 63;
    int g = r >> 3, jl = r & 7;
    size_t go = (size_t)(g * 512 + jblk + jl) * 512 + c16 * 8;
    unsigned so = (unsigned)(r * WSTR + c16 * 8) * 2;
    *reinterpret_cast<uint4*>(smem + so) =
        *reinterpret_cast<const uint4*>(whi + go);
    *reinterpret_cast<uint4*>(smem + W_LO + so) =
        *reinterpret_cast<const uint4*>(wlo + go);
  }

  float c_st[2][2];
  c_st[0][0] = c_st[0][1] = c_st[1][0] = c_st[1][1] = 0.f;

  const int er = lane >> 2;
  const int ec = (lane & 3) << 1;
  const int jg = jblk + ec;

  // A-chunk loader: 64 rows x 256 k (hi+lo) = 64 KB, 16 cp.async16/thread
  const int r0 = tid >> 2;
  const int c0 = tid & 3;
  auto load_chunk = [&](const __nv_bfloat16* hhi, const __nv_bfloat16* hlo,
                        int ch) {
    const int k0 = ch << 8;
    const unsigned base = sb + A_BASE + (unsigned)ch * A_BUFSZ;
#pragma unroll
    for (int e = 0; e < 8; e++) {
      int c16 = c0 + (e << 2);
      unsigned so = (unsigned)(r0 * ASTR + c16 * 8) * 2;
      size_t go = (size_t)r0 * 512 + k0 + c16 * 8;
      cp_async16(base + so, hhi + go);
      cp_async16(base + A_LOSZ + so, hlo + go);
    }
  };

  for (int t = 0; t < T; t++) {
    const int tt = dir ? (T - 1 - t) : t;
    const int par = t & 1;
    const __nv_bfloat16* hhi = g_hbf_hi[par][dir];
    const __nv_bfloat16* hlo = g_hbf_lo[par][dir];
    __nv_bfloat16* nhi = g_hbf_hi[par ^ 1][dir];
    __nv_bfloat16* nlo = g_hbf_lo[par ^ 1][dir];

    __syncthreads();   // prev step fully done (smem reuse safe)
    load_chunk(hhi, hlo, 0);
    cp_commit();
    load_chunk(hhi, hlo, 1);
    // pre-gate slice for this step: 64 b x 32 cols fp32 = 8 KB
#pragma unroll
    for (int e = 0; e < 2; e++) {
      int cid = tid + (e << 8);
      int b = cid >> 3, seg = cid & 7;
      const float* src =
          pre + ((size_t)tt * 64 + b) * 2048 + (seg >> 1) * 512 + jblk +
          (seg & 1) * 4;
      cp_async16(sb + PRE_OFF + (unsigned)(b * 32 + seg * 4) * 4, src);
    }
    cp_commit();

    float acc[4][4];
#pragma unroll
    for (int g = 0; g < 4; g++)
#pragma unroll
      for (int q = 0; q < 4; q++) acc[g][q] = 0.f;

#pragma unroll
    for (int ch = 0; ch < 2; ch++) {
      if (ch == 0) cp_wait<1>(); else cp_wait<0>();
      __syncthreads();
      const unsigned abase = sb + A_BASE + (unsigned)ch * A_BUFSZ;
      const int kloc = kh << 7;          // 0 or 128 within 256-k chunk
      const int kglob = (ch << 8) + kloc;
#pragma unroll
      for (int kk = 0; kk < 128; kk += 16) {
        unsigned ah[4], al[4], bh[2][4], bl[2][4];
        unsigned aoff =
            (unsigned)((wm + lrow16) * ASTR + kloc + kk + lcol8) * 2;
        ldmx4(ah, abase + aoff);
        ldmx4(al, abase + A_LOSZ + aoff);
#pragma unroll
        for (int ni = 0; ni < 2; ni++) {
          unsigned woff =
              (unsigned)((ni * 16 + lrow16) * WSTR + kglob + kk + lcol8) * 2;
          ldmx4(bh[ni], sb + woff);
          ldmx4(bl[ni], sb + W_LO + woff);
        }
#pragma unroll
        for (int g = 0; g < 4; g++) {
          unsigned h0 = bh[g >> 1][g & 1], h1 = bh[g >> 1][2 + (g & 1)];
          unsigned l0 = bl[g >> 1][g & 1], l1 = bl[g >> 1][2 + (g & 1)];
          hmma(acc[g], ah, h0, h1);
          hmma(acc[g], ah, l0, l1);
          hmma(acc[g], al, h0, h1);
        }
      }
    }

    // split-K reduce: upper half dumps, lower half combines + epilogue
    __syncthreads();
    if (kh == 1) {
#pragma unroll
      for (int g = 0; g < 4; g++)
        red[(mw * 4 + g) * 32 + lane] =
            make_float4(acc[g][0], acc[g][1], acc[g][2], acc[g][3]);
    }
    __syncthreads();

    if (kh == 0) {
#pragma unroll
      for (int g = 0; g < 4; g++) {
        float4 r = red[(mw * 4 + g) * 32 + lane];
        acc[g][0] += r.x; acc[g][1] += r.y; acc[g][2] += r.z; acc[g][3] += r.w;
      }
#pragma unroll
      for (int i = 0; i < 2; i++) {
        int b = wm + er + i * 8;
        const float* pp = pre_s + b * 32 + ec;
        float2 pi = *reinterpret_cast<const float2*>(pp);
        float2 pf = *reinterpret_cast<const float2*>(pp + 8);
        float2 pg = *reinterpret_cast<const float2*>(pp + 16);
        float2 po = *reinterpret_cast<const float2*>(pp + 24);
        float gi0 = acc[0][i * 2] + pi.x, gi1 = acc[0][i * 2 + 1] + pi.y;
        float gf0 = acc[1][i * 2] + pf.x, gf1 = acc[1][i * 2 + 1] + pf.y;
        float gg0 = acc[2][i * 2] + pg.x, gg1 = acc[2][i * 2 + 1] + pg.y;
        float go0 = acc[3][i * 2] + po.x, go1 = acc[3][i * 2 + 1] + po.y;
        float c0 = sigf(gf0) * c_st[i][0] + sigf(gi0) * tanhf_fast(gg0);
        float c1 = sigf(gf1) * c_st[i][1] + sigf(gi1) * tanhf_fast(gg1);
        c_st[i][0] = c0; c_st[i][1] = c1;
        float h0 = sigf(go0) * tanhf_fast(c0);
        float h1 = sigf(go1) * tanhf_fast(c1);
        *reinterpret_cast<float2*>(
            &out[((size_t)tt * 64 + b) * 1024 + dir * 512 + jg]) =
            make_float2(h0, h1);
        __nv_bfloat16 h0h = __float2bfloat16(h0);
        __nv_bfloat16 h1h = __float2bfloat16(h1);
        __nv_bfloat16 h0l = __float2bfloat16(h0 - __bfloat162float(h0h));
        __nv_bfloat16 h1l = __float2bfloat16(h1 - __bfloat162float(h1h));
        __nv_bfloat162 vh; vh.x = h0h; vh.y = h1h;
        __nv_bfloat162 vl; vl.x = h0l; vl.y = h1l;
        *reinterpret_cast<__nv_bfloat162*>(&nhi[b * 512 + jg]) = vh;
        *reinterpret_cast<__nv_bfloat162*>(&nlo[b * 512 + jg]) = vl;
      }
    }

    // per-direction grid barrier before next step reads nhi/nlo
    if (t != T - 1) {
      __threadfence();
      __syncthreads();
      if (tid == 0) {
        unsigned target = (unsigned)(t + 1);
        if (atomicAdd(&g_barcnt[dir], 1u) == NBLK_PER_DIR - 1) {
          g_barcnt[dir] = 0;
          __threadfence();
          atomicExch((unsigned*)&g_bargen[dir], target);
        } else {
          while (g_bargen[dir] < target) __nanosleep(32);
        }
      }
      __syncthreads();
    }
  }
}

// ---------------------------------------------------------------------------
__global__ __launch_bounds__(256)
void fc_kernel(const float* __restrict__ inp,
               const float* __restrict__ Wt,
               const float* __restrict__ bias,
               float* __restrict__ out) {
  __shared__ float rs[8][1024];
  int r0 = blockIdx.x << 3;
#pragma unroll
  for (int l = threadIdx.x; l < 2048; l += 256) {
    int r = l >> 8, f4 = (l & 255) << 2;
    *reinterpret_cast<float4*>(&rs[r][f4]) =
        *reinterpret_cast<const float4*>(&inp[(size_t)(r0 + r) * 1024 + f4]);
  }
  __syncthreads();
  int r = threadIdx.x >> 5;
  int tg = threadIdx.x & 31;
  int tag2 = tg + 32;
  bool has2 = (tag2 < TAGS);
  float a0 = 0.f, a1 = 0.f;
  for (int k = 0; k < 1024; k += 4) {
    float4 xv = *reinterpret_cast<const float4*>(&rs[r][k]);
    float4 w0 = *reinterpret_cast<const float4*>(&Wt[(size_t)tg * 1024 + k]);
    a0 += xv.x * w0.x + xv.y * w0.y + xv.z * w0.z + xv.w * w0.w;
    if (has2) {
      float4 w1 = *reinterpret_cast<const float4*>(&Wt[(size_t)tag2 * 1024 + k]);
      a1 += xv.x * w1.x + xv.y * w1.y + xv.z * w1.z + xv.w * w1.w;
    }
  }
  int row = r0 + r;
  int tq = row >> 6, bb = row & 63;
  size_t obase = ((size_t)bb * T + tq) * TAGS;
  out[obase + tg] = a0 + bias[tg];
  if (has2) out[obase + tag2] = a1 + bias[tag2];
}

// ---------------------------------------------------------------------------
extern "C" void kernel_launch(void* const* d_in, const int* in_sizes, int n_in,
                              void* d_out, int out_size) {
  const int* x = (const int*)d_in[0];
  const float* emb = (const float*)d_in[2];
  const float* Wih_f1 = (const float*)d_in[3];
  const float* Whh_f1 = (const float*)d_in[4];
  const float* bih_f1 = (const float*)d_in[5];
  const float* bhh_f1 = (const float*)d_in[6];
  const float* Wih_b1 = (const float*)d_in[7];
  const float* Whh_b1 = (const float*)d_in[8];
  const float* bih_b1 = (const float*)d_in[9];
  const float* bhh_b1 = (const float*)d_in[10];
  const float* Wih_f2 = (const float*)d_in[11];
  const float* Whh_f2 = (const float*)d_in[12];
  const float* bih_f2 = (const float*)d_in[13];
  const float* bhh_f2 = (const float*)d_in[14];
  const float* Wih_b2 = (const float*)d_in[15];
  const float* Whh_b2 = (const float*)d_in[16];
  const float* bih_b2 = (const float*)d_in[17];
  const float* bhh_b2 = (const float*)d_in[18];
  const float* fcW = (const float*)d_in[19];
  const float* fcb = (const float*)d_in[20];
  float* out = (float*)d_out;

  float *xs, *pre_f, *pre_b, *out1, *out2;
  __nv_bfloat16 *ahi, *alo, *whi, *wlo, *whhhi, *whhlo;
  cudaGetSymbolAddress((void**)&xs, g_xs);
  cudaGetSymbolAddress((void**)&pre_f, g_pre_f);
  cudaGetSymbolAddress((void**)&pre_b, g_pre_b);
  cudaGetSymbolAddress((void**)&out1, g_out1);
  cudaGetSymbolAddress((void**)&out2, g_out2);
  cudaGetSymbolAddress((void**)&ahi, g_ahi);
  cudaGetSymbolAddress((void**)&alo, g_alo);
  cudaGetSymbolAddress((void**)&whi, g_whi);
  cudaGetSymbolAddress((void**)&wlo, g_wlo);
  cudaGetSymbolAddress((void**)&whhhi, g_whhhi);
  cudaGetSymbolAddress((void**)&whhlo, g_whhlo);

  constexpr int LSTM_SMEM = 209920 + 8192;        // 218,112 B
  constexpr int GEMM_SMEM = 2 * 2 * 128 * 40 * 2; // 40,960 B
  static bool attr_set = false;
  if (!attr_set) {
    cudaFuncSetAttribute(lstm_persistent,
                         cudaFuncAttributeMaxDynamicSharedMemorySize, LSTM_SMEM);
    cudaFuncSetAttribute(gemm_split_kernel<512>,
                         cudaFuncAttributeMaxDynamicSharedMemorySize, GEMM_SMEM);
    cudaFuncSetAttribute(gemm_split_kernel<1024>,
                         cudaFuncAttributeMaxDynamicSharedMemorySize, GEMM_SMEM);
    attr_set = true;
  }

  dim3 gg(G / 128, M / 128);   // (16, 128)

  embed_kernel<<<M, 128>>>(x, emb);
  split_kernel<<<(M * E + 255) / 256, 256>>>(xs, ahi, alo, M * E);

  // Layer 1 (K = 512)
  init_layer_kernel<<<(2 * 2 * B * H + 255) / 256, 256>>>();
  split_kernel<<<(G * E + 255) / 256, 256>>>(Wih_f1, whi, wlo, G * E);
  gemm_split_kernel<512><<<gg, 256, GEMM_SMEM>>>(ahi, alo, whi, wlo,
                                                 bih_f1, bhh_f1, pre_f);
  split_kernel<<<(G * E + 255) / 256, 256>>>(Wih_b1, whi, wlo, G * E);
  gemm_split_kernel<512><<<gg, 256, GEMM_SMEM>>>(ahi, alo, whi, wlo,
                                                 bih_b1, bhh_b1, pre_b);
  split_kernel<<<(GH + 255) / 256, 256>>>(Whh_f1, whhhi, whhlo, GH);
  split_kernel<<<(GH + 255) / 256, 256>>>(Whh_b1, whhhi + GH, whhlo + GH, GH);
  lstm_persistent<<<2 * NBLK_PER_DIR, 256, LSTM_SMEM>>>(pre_f, pre_b,
                                                        whhhi, whhlo, out1);

  // Layer 2 (K = 1024)
  init_layer_kernel<<<(2 * 2 * B * H + 255) / 256, 256>>>();
  split_kernel<<<(M * 1024 + 255) / 256, 256>>>(out1, ahi, alo, M * 1024);
  split_kernel<<<(G * 1024 + 255) / 256, 256>>>(Wih_f2, whi, wlo, G * 1024);
  gemm_split_kernel<1024><<<gg, 256, GEMM_SMEM>>>(ahi, alo, whi, wlo,
                                                  bih_f2, bhh_f2, pre_f);
  split_kernel<<<(G * 1024 + 255) / 256, 256>>>(Wih_b2, whi, wlo, G * 1024);
  gemm_split_kernel<1024><<<gg, 256, GEMM_SMEM>>>(ahi, alo, whi, wlo,
                                                  bih_b2, bhh_b2, pre_b);
  split_kernel<<<(GH + 255) / 256, 256>>>(Whh_f2, whhhi, whhlo, GH);
  split_kernel<<<(GH + 255) / 256, 256>>>(Whh_b2, whhhi + GH, whhlo + GH, GH);
  lstm_persistent<<<2 * NBLK_PER_DIR, 256, LSTM_SMEM>>>(pre_f, pre_b,
                                                        whhhi, whhlo, out2);

  fc_kernel<<<M / 8, 256>>>(out2, fcW, fcb, out);
}